// round 7
// baseline (speedup 1.0000x reference)
#include <cuda_runtime.h>
#include <cuda_bf16.h>
#include <cuda_fp16.h>
#include <math.h>

// ---------------- problem constants ----------------
#define HH 8
#define DD 16
#define FF 128
#define F3 384
#define NLAYER 2
#define NTYPE 3
#define NREL 4
#define NTOT 80000
#define KRTOT 120000
#define ETOT 600000
#define BKPAD 40           // smem k-stride in bf16 (80 bytes): conflict-free ldmatrix

#define KQVW_ELEMS (NLAYER * NTYPE * F3 * FF)   // 294912
#define OUTW_ELEMS (NLAYER * NTYPE * FF * FF)   //  98304
#define WTOT (KQVW_ELEMS + OUTW_ELEMS)

// host-side metadata
static const int h_NS[3]    = {50000, 20000, 10000};
static const int h_OFFS[4]  = {0, 50000, 70000, 80000};
static const int h_ES[4]    = {300000, 150000, 100000, 50000};
static const int h_EBASE[4] = {0, 300000, 450000, 550000};
static const int h_SRCT[4]  = {0, 0, 2, 2};
static const int h_DSTT[4]  = {0, 1, 0, 1};
static const int h_KROFF[4] = {0, 50000, 100000, 110000};

// ---------------- device scratch ----------------
__device__ __align__(16) float g_x0[NTOT * FF];
__device__ __align__(16) float g_x1[NTOT * FF];
__device__ __align__(16) float g_kqv[NTOT * F3];
__device__ __align__(16) float g_alpha[ETOT * HH];
__device__ __align__(16) float g_denom[NTOT * HH];
__device__ __align__(16) float g_agg[NTOT * FF];
// fp16 gather buffers (L2-resident working set: 30+30+20 = 80MB)
__device__ __align__(16) __half g_krh[KRTOT * FF];
__device__ __align__(16) __half g_vrh[KRTOT * FF];
__device__ __align__(16) __half g_qh[NTOT * FF];
// bf16x2 split planes for tensor-core GEMM
__device__ __align__(16) __nv_bfloat16 g_ah[NTOT * FF];
__device__ __align__(16) __nv_bfloat16 g_al[NTOT * FF];
__device__ __align__(16) __nv_bfloat16 g_wh[WTOT];   // weights, [n][k] k-major
__device__ __align__(16) __nv_bfloat16 g_wl[WTOT];

__device__ __forceinline__ float* sel_buf(int s) {
    if (s == 0) return g_x0;
    if (s == 1) return g_x1;
    if (s == 2) return g_agg;
    return g_kqv;
}

__device__ __forceinline__ float gelu_f(float x) {
    return 0.5f * x * (1.f + erff(x * 0.70710678118654752440f));
}

// ---------------- utility kernels ----------------

__global__ void copyin_kernel(const float* __restrict__ xg,
                              const float* __restrict__ xd,
                              const float* __restrict__ xr) {
    long i = (long)blockIdx.x * blockDim.x + threadIdx.x;
    if (i >= (long)NTOT * FF) return;
    const long n1 = 50000L * FF, n2 = 70000L * FF;
    float v;
    if (i < n1)      v = xg[i];
    else if (i < n2) v = xd[i - n1];
    else             v = xr[i - n2];
    g_x0[i] = v;
}

__global__ void init_kernel() {
    long i = (long)blockIdx.x * blockDim.x + threadIdx.x;
    if (i < (long)NTOT * HH) g_denom[i] = 0.f;
    if (i < (long)NTOT * FF) g_agg[i] = 0.f;
}

// split weights into transposed (k-major) bf16 hi/lo planes. Runs once per call.
__global__ void splitw_kernel(const float* __restrict__ Wkqv,
                              const float* __restrict__ Wout) {
    int idx = blockIdx.x * blockDim.x + threadIdx.x;
    if (idx >= WTOT) return;
    float val;
    if (idx < KQVW_ELEMS) {
        int lt = idx / (F3 * FF);
        int rem = idx - lt * (F3 * FF);
        int n = rem / FF, k = rem % FF;
        val = Wkqv[(long)lt * FF * F3 + (long)k * F3 + n];
    } else {
        int j = idx - KQVW_ELEMS;
        int lt = j / (FF * FF);
        int rem = j - lt * (FF * FF);
        int n = rem / FF, k = rem % FF;
        val = Wout[(long)lt * FF * FF + (long)k * FF + n];
    }
    __nv_bfloat16 hi = __float2bfloat16_rn(val);
    __nv_bfloat16 lo = __float2bfloat16_rn(val - __bfloat162float(hi));
    g_wh[idx] = hi;
    g_wl[idx] = lo;
}

// split activations (optionally gelu) into bf16 hi/lo planes, 8 elems/thread
__global__ void split_kernel(int src_sel, int act) {
    long i8 = ((long)blockIdx.x * blockDim.x + threadIdx.x) * 8;
    if (i8 >= (long)NTOT * FF) return;
    const float* s = sel_buf(src_sel);
    float v[8];
    *(float4*)&v[0] = *(const float4*)&s[i8];
    *(float4*)&v[4] = *(const float4*)&s[i8 + 4];
    __nv_bfloat16 h[8], l[8];
#pragma unroll
    for (int j = 0; j < 8; j++) {
        float x = act ? gelu_f(v[j]) : v[j];
        h[j] = __float2bfloat16_rn(x);
        l[j] = __float2bfloat16_rn(x - __bfloat162float(h[j]));
    }
    *(uint4*)&g_ah[i8] = *(const uint4*)&h[0];
    *(uint4*)&g_al[i8] = *(const uint4*)&l[0];
}

// ---------------- tensor-core GEMM ----------------
#define LDSM4(r, addr) \
    asm volatile("ldmatrix.sync.aligned.m8n8.x4.shared.b16 {%0,%1,%2,%3}, [%4];" \
        : "=r"((r)[0]), "=r"((r)[1]), "=r"((r)[2]), "=r"((r)[3]) : "r"(addr))

#define MMA16816(c, a0, a1, a2, a3, b0, b1) \
    asm volatile("mma.sync.aligned.m16n8k16.row.col.f32.bf16.bf16.f32 " \
        "{%0,%1,%2,%3}, {%4,%5,%6,%7}, {%8,%9}, {%0,%1,%2,%3};" \
        : "+f"((c)[0]), "+f"((c)[1]), "+f"((c)[2]), "+f"((c)[3]) \
        : "r"(a0), "r"(a1), "r"(a2), "r"(a3), "r"(b0), "r"(b1))

// qpack==1: columns [128,256) of the kqv result are also stored as fp16 into g_qh
__global__ __launch_bounds__(256)
void mma_gemm(long a_row_off, long b_off, const float* __restrict__ bias,
              int c_sel, float* c_ext, long c_off,
              int M, int N, int epi, int qpack,
              int x_sel, long x_off, const float* __restrict__ skipp) {
    __shared__ __align__(16) __nv_bfloat16 sAh[128 * BKPAD];
    __shared__ __align__(16) __nv_bfloat16 sAl[128 * BKPAD];
    __shared__ __align__(16) __nv_bfloat16 sBh[128 * BKPAD];
    __shared__ __align__(16) __nv_bfloat16 sBl[128 * BKPAD];

    int t = threadIdx.x;
    int bm = blockIdx.y * 128, bn = blockIdx.x * 128;
    int lane = t & 31, wid = t >> 5;
    int wm = (wid & 1) * 64, wn = (wid >> 1) * 32;

    float* C = (c_sel >= 0 ? sel_buf(c_sel) : c_ext) + c_off;

    float acc[4][4][4];
#pragma unroll
    for (int a = 0; a < 4; a++)
#pragma unroll
        for (int b = 0; b < 4; b++)
#pragma unroll
            for (int c = 0; c < 4; c++) acc[a][b][c] = 0.f;

    for (int kc = 0; kc < 128; kc += 32) {
#pragma unroll
        for (int i = 0; i < 4; i++) {
            int id = t + i * 256;
            int j = id & 3, m = (id >> 2) & 127, pl = id >> 9;
            const __nv_bfloat16* src = pl ? g_al : g_ah;
            __nv_bfloat16* dstS = pl ? sAl : sAh;
            uint4 v = make_uint4(0u, 0u, 0u, 0u);
            int gr = bm + m;
            if (gr < M)
                v = *(const uint4*)(src + (a_row_off + gr) * 128 + kc + j * 8);
            *(uint4*)(dstS + m * BKPAD + j * 8) = v;
        }
#pragma unroll
        for (int i = 0; i < 4; i++) {
            int id = t + i * 256;
            int j = id & 3, n = (id >> 2) & 127, pl = id >> 9;
            const __nv_bfloat16* src = pl ? g_wl : g_wh;
            __nv_bfloat16* dstS = pl ? sBl : sBh;
            uint4 v = *(const uint4*)(src + b_off + (long)(bn + n) * 128 + kc + j * 8);
            *(uint4*)(dstS + n * BKPAD + j * 8) = v;
        }
        __syncthreads();

#pragma unroll
        for (int k16 = 0; k16 < 32; k16 += 16) {
            unsigned af[4][2][4];
            int arow = wm + (lane & 15);
            int akoff = k16 + (lane >> 4) * 8;
#pragma unroll
            for (int mi = 0; mi < 4; mi++) {
                unsigned ah = (unsigned)__cvta_generic_to_shared(
                    sAh + (arow + mi * 16) * BKPAD + akoff);
                unsigned al = (unsigned)__cvta_generic_to_shared(
                    sAl + (arow + mi * 16) * BKPAD + akoff);
                LDSM4(af[mi][0], ah);
                LDSM4(af[mi][1], al);
            }
#pragma unroll
            for (int p = 0; p < 2; p++) {
                int nrow = wn + p * 16 + ((lane >> 4) & 1) * 8 + (lane & 7);
                int bkoff = k16 + ((lane >> 3) & 1) * 8;
                unsigned bh[4], bl[4];
                unsigned bha = (unsigned)__cvta_generic_to_shared(
                    sBh + nrow * BKPAD + bkoff);
                unsigned bla = (unsigned)__cvta_generic_to_shared(
                    sBl + nrow * BKPAD + bkoff);
                LDSM4(bh, bha);
                LDSM4(bl, bla);
#pragma unroll
                for (int mi = 0; mi < 4; mi++) {
                    MMA16816(acc[mi][2 * p], af[mi][0][0], af[mi][0][1], af[mi][0][2], af[mi][0][3], bh[0], bh[1]);
                    MMA16816(acc[mi][2 * p], af[mi][0][0], af[mi][0][1], af[mi][0][2], af[mi][0][3], bl[0], bl[1]);
                    MMA16816(acc[mi][2 * p], af[mi][1][0], af[mi][1][1], af[mi][1][2], af[mi][1][3], bh[0], bh[1]);
                    MMA16816(acc[mi][2 * p + 1], af[mi][0][0], af[mi][0][1], af[mi][0][2], af[mi][0][3], bh[2], bh[3]);
                    MMA16816(acc[mi][2 * p + 1], af[mi][0][0], af[mi][0][1], af[mi][0][2], af[mi][0][3], bl[2], bl[3]);
                    MMA16816(acc[mi][2 * p + 1], af[mi][1][0], af[mi][1][1], af[mi][1][2], af[mi][1][3], bh[2], bh[3]);
                }
            }
        }
        __syncthreads();
    }

    float s = 0.f, oms = 0.f;
    const float* X = 0;
    if (epi) {
        float sv = *skipp;
        s = 1.f / (1.f + expf(-sv));
        oms = 1.f - s;
        X = sel_buf(x_sel) + x_off;
    }
#pragma unroll
    for (int mi = 0; mi < 4; mi++) {
#pragma unroll
        for (int nj = 0; nj < 4; nj++) {
            int rbase = bm + wm + mi * 16 + (lane >> 2);
            int col = bn + wn + nj * 8 + (lane & 3) * 2;
            float2 b2 = *(const float2*)&bias[col];
#pragma unroll
            for (int h = 0; h < 2; h++) {
                int gr = rbase + h * 8;
                if (gr >= M) continue;
                float o0 = acc[mi][nj][h * 2 + 0] + b2.x;
                float o1 = acc[mi][nj][h * 2 + 1] + b2.y;
                if (!epi) {
                    *(float2*)&C[(long)gr * N + col] = make_float2(o0, o1);
                    if (qpack && col >= 128 && col < 256) {
                        *(__half2*)&g_qh[(a_row_off + gr) * 128 + (col - 128)] =
                            __floats2half2_rn(o0, o1);
                    }
                } else {
                    float2 xv = *(const float2*)&X[(long)gr * 128 + col];
                    float n0 = s * o0 + oms * xv.x;
                    float n1 = s * o1 + oms * xv.y;
                    *(float2*)&C[(long)gr * N + col] =
                        make_float2(fmaxf(n0, 0.f) + xv.x, fmaxf(n1, 0.f) + xv.y);
                }
            }
        }
    }
}

// ---------------- edge-phase kernels ----------------

// k_r/v_r transform, output fp16
__global__ __launch_bounds__(256)
void krvr_kernel(const float* __restrict__ Ak, const float* __restrict__ Av,
                 int l, int r, int st_off, int nsrc, int kroff) {
    __shared__ float sA[2][HH][DD][DD];
    int tid = threadIdx.x;
    const float* Akb = Ak + (long)(l * NREL + r) * HH * DD * DD;
    const float* Avb = Av + (long)(l * NREL + r) * HH * DD * DD;
    float* sflat = &sA[0][0][0][0];
    for (int i = tid; i < 2048; i += 256) {
        sflat[i] = Akb[i];
        sflat[2048 + i] = Avb[i];
    }
    __syncthreads();

    int half = tid >> 7;
    int h = (tid & 127) >> 4;
    int e = tid & 15;
    int n0 = blockIdx.x * 16;
    __half* dst = half ? g_vrh : g_krh;
    int kqv_off = half ? 256 : 0;

    for (int ni = 0; ni < 16; ni++) {
        int n = n0 + ni;
        if (n >= nsrc) break;
        const float* srcp = g_kqv + (long)(st_off + n) * F3 + kqv_off + h * DD;
        float acc = 0.f;
#pragma unroll
        for (int d = 0; d < DD; d++) acc += srcp[d] * sA[half][h][d][e];
        dst[(long)(kroff + n) * FF + h * DD + e] = __float2half_rn(acc);
    }
}

// one warp per edge: attention logits (fp16 gathers) -> exp -> denominator
__global__ __launch_bounds__(256)
void alpha_kernel(const int* __restrict__ src, const int* __restrict__ dst,
                  const float* __restrict__ prel,
                  int E, int l, int r, int dt_off, int kroff, int ebase) {
    int warp = (blockIdx.x * blockDim.x + threadIdx.x) >> 5;
    int lane = threadIdx.x & 31;
    if (warp >= E) return;
    int sn = src[warp], dn = dst[warp];
    uint2 qu = *(const uint2*)(g_qh  + (long)(dt_off + dn) * FF + lane * 4);
    uint2 ku = *(const uint2*)(g_krh + (long)(kroff + sn) * FF + lane * 4);
    float2 qa = __half22float2(*(__half2*)&qu.x);
    float2 qb = __half22float2(*(__half2*)&qu.y);
    float2 ka = __half22float2(*(__half2*)&ku.x);
    float2 kb = __half22float2(*(__half2*)&ku.y);
    float p = qa.x * ka.x + qa.y * ka.y + qb.x * kb.x + qb.y * kb.y;
    p += __shfl_xor_sync(0xFFFFFFFFu, p, 1);
    p += __shfl_xor_sync(0xFFFFFFFFu, p, 2);
    if ((lane & 3) == 0) {
        int h = lane >> 2;
        float a = p * prel[(l * NREL + r) * HH + h] * 0.25f;
        float ex = expf(a);
        g_alpha[(long)(ebase + warp) * HH + h] = ex;
        atomicAdd(&g_denom[(long)(dt_off + dn) * HH + h], ex);
    }
}

// one warp per edge: out[dst] += v_r[src] * softmax_weight (fp16 gather, v4 RED)
__global__ __launch_bounds__(256)
void agg_kernel(const int* __restrict__ src, const int* __restrict__ dst,
                int E, int dt_off, int kroff, int ebase) {
    int warp = (blockIdx.x * blockDim.x + threadIdx.x) >> 5;
    int lane = threadIdx.x & 31;
    if (warp >= E) return;
    int sn = src[warp], dn = dst[warp];
    int h = lane >> 2;
    long nb = (long)(dt_off + dn) * HH + h;
    float ex  = g_alpha[(long)(ebase + warp) * HH + h];
    float den = g_denom[nb];
    float w = ex / den;
    uint2 vu = *(const uint2*)(g_vrh + (long)(kroff + sn) * FF + lane * 4);
    float2 va = __half22float2(*(__half2*)&vu.x);
    float2 vb = __half22float2(*(__half2*)&vu.y);
    float* o = g_agg + (long)(dt_off + dn) * FF + lane * 4;
    asm volatile("red.global.add.v4.f32 [%0], {%1,%2,%3,%4};"
                 :: "l"(o), "f"(va.x * w), "f"(va.y * w),
                    "f"(vb.x * w), "f"(vb.y * w)
                 : "memory");
}

// ---------------- launch ----------------
extern "C" void kernel_launch(void* const* d_in, const int* in_sizes, int n_in,
                              void* d_out, int out_size) {
    const float* xg   = (const float*)d_in[0];
    const float* xd   = (const float*)d_in[1];
    const float* xr   = (const float*)d_in[2];
    const float* Wkqv = (const float*)d_in[3];
    const float* bkqv = (const float*)d_in[4];
    const float* Ak   = (const float*)d_in[5];
    const float* Av   = (const float*)d_in[6];
    const float* prel = (const float*)d_in[7];
    const float* Wout = (const float*)d_in[8];
    const float* bout = (const float*)d_in[9];
    const float* skip = (const float*)d_in[10];
    const int* ei[4] = {(const int*)d_in[11], (const int*)d_in[12],
                        (const int*)d_in[13], (const int*)d_in[14]};
    float* outp = (float*)d_out;

    const int NELEM_BLOCKS = (NTOT * FF + 255) / 256;
    const int SPLIT_BLOCKS = (NTOT * FF / 8 + 255) / 256;

    copyin_kernel<<<NELEM_BLOCKS, 256>>>(xg, xd, xr);
    splitw_kernel<<<(WTOT + 255) / 256, 256>>>(Wkqv, Wout);

    for (int l = 0; l < NLAYER; l++) {
        int a_x = (l == 0) ? 0 : 1;

        // 1) split x into bf16 planes
        split_kernel<<<SPLIT_BLOCKS, 256>>>(a_x, 0);

        // 2) kqv = x @ Wkqv + bkqv (tensor cores), q also packed to fp16
        for (int t = 0; t < NTYPE; t++) {
            dim3 grid(F3 / 128, (h_NS[t] + 127) / 128);
            mma_gemm<<<grid, 256>>>(
                (long)h_OFFS[t],
                (long)(l * NTYPE + t) * F3 * FF,
                bkqv + (long)(l * NTYPE + t) * F3,
                3 /*g_kqv*/, 0, (long)h_OFFS[t] * F3,
                h_NS[t], F3, 0, 1 /*qpack*/, 0, 0, 0);
        }

        // 3) reset softmax/aggregation state
        init_kernel<<<NELEM_BLOCKS, 256>>>();

        // 4) relation-specific k_r, v_r (fp16 out)
        for (int r = 0; r < NREL; r++) {
            int st = h_SRCT[r];
            krvr_kernel<<<(h_NS[st] + 15) / 16, 256>>>(
                Ak, Av, l, r, h_OFFS[st], h_NS[st], h_KROFF[r]);
        }

        // 5) edge logits + exp + denominator
        for (int r = 0; r < NREL; r++) {
            int E = h_ES[r];
            alpha_kernel<<<(E * 32 + 255) / 256, 256>>>(
                ei[r], ei[r] + E, prel, E, l, r,
                h_OFFS[h_DSTT[r]], h_KROFF[r], h_EBASE[r]);
        }

        // 6) weighted scatter-add of v_r
        for (int r = 0; r < NREL; r++) {
            int E = h_ES[r];
            agg_kernel<<<(E * 32 + 255) / 256, 256>>>(
                ei[r], ei[r] + E, E,
                h_OFFS[h_DSTT[r]], h_KROFF[r], h_EBASE[r]);
        }

        // 7) split gelu(agg) into bf16 planes
        split_kernel<<<SPLIT_BLOCKS, 256>>>(2, 1);

        // 8) out GEMM + skip-blend + relu + residual
        for (int t = 0; t < NTYPE; t++) {
            dim3 grid(FF / 128, (h_NS[t] + 127) / 128);
            int c_sel = (l == 0) ? 1 : -1;
            mma_gemm<<<grid, 256>>>(
                (long)h_OFFS[t],
                (long)KQVW_ELEMS + (long)(l * NTYPE + t) * FF * FF,
                bout + (long)(l * NTYPE + t) * FF,
                c_sel, outp, (long)h_OFFS[t] * FF,
                h_NS[t], FF, 1, 0,
                a_x, (long)h_OFFS[t] * FF,
                skip + l * NTYPE + t);
        }
    }
    (void)in_sizes; (void)n_in; (void)out_size;
}

// round 8
// speedup vs baseline: 1.1852x; 1.1852x over previous
#include <cuda_runtime.h>
#include <cuda_bf16.h>
#include <cuda_fp16.h>
#include <math.h>

// ---------------- problem constants ----------------
#define HH 8
#define DD 16
#define FF 128
#define F3 384
#define NLAYER 2
#define NTYPE 3
#define NREL 4
#define NTOT 80000
#define KRTOT 120000
#define ETOT 600000
#define BKPAD 40           // smem k-stride in bf16 (80 bytes): conflict-free ldmatrix

#define KQVW_ELEMS (NLAYER * NTYPE * F3 * FF)   // 294912
#define OUTW_ELEMS (NLAYER * NTYPE * FF * FF)   //  98304
#define WTOT (KQVW_ELEMS + OUTW_ELEMS)

// host-side metadata
static const int h_NS[3]    = {50000, 20000, 10000};
static const int h_OFFS[4]  = {0, 50000, 70000, 80000};
static const int h_ES[4]    = {300000, 150000, 100000, 50000};
static const int h_SRCT[4]  = {0, 0, 2, 2};
static const int h_DSTT[4]  = {0, 1, 0, 1};
static const int h_KROFF[4] = {0, 50000, 100000, 110000};

// ---------------- device scratch ----------------
__device__ __align__(16) float g_x0[NTOT * FF];
__device__ __align__(16) float g_x1[NTOT * FF];
__device__ __align__(16) float g_kqv[NTOT * F3];
// fp16 gather buffers (L2-resident)
__device__ __align__(16) __half g_krh[KRTOT * FF];
__device__ __align__(16) __half g_vrh[KRTOT * FF];
// bf16x2 split planes for tensor-core GEMM
__device__ __align__(16) __nv_bfloat16 g_ah[NTOT * FF];
__device__ __align__(16) __nv_bfloat16 g_al[NTOT * FF];
__device__ __align__(16) __nv_bfloat16 g_wh[WTOT];   // weights, [n][k] k-major
__device__ __align__(16) __nv_bfloat16 g_wl[WTOT];
// CSR over global destinations
__device__ int g_deg[NTOT];
__device__ int g_off[NTOT + 1];
__device__ int g_cursor[NTOT];
__device__ int g_csr[ETOT];      // (r << 20) | (kroff + src)

__device__ __forceinline__ float gelu_f(float x) {
    return 0.5f * x * (1.f + erff(x * 0.70710678118654752440f));
}

// ---------------- setup kernels ----------------

__global__ void copyin_kernel(const float* __restrict__ xg,
                              const float* __restrict__ xd,
                              const float* __restrict__ xr) {
    long i = (long)blockIdx.x * blockDim.x + threadIdx.x;
    if (i >= (long)NTOT * FF) return;
    const long n1 = 50000L * FF, n2 = 70000L * FF;
    float v;
    if (i < n1)      v = xg[i];
    else if (i < n2) v = xd[i - n1];
    else             v = xr[i - n2];
    g_x0[i] = v;
}

// split weights into transposed (k-major) bf16 hi/lo planes
__global__ void splitw_kernel(const float* __restrict__ Wkqv,
                              const float* __restrict__ Wout) {
    int idx = blockIdx.x * blockDim.x + threadIdx.x;
    if (idx >= WTOT) return;
    float val;
    if (idx < KQVW_ELEMS) {
        int lt = idx / (F3 * FF);
        int rem = idx - lt * (F3 * FF);
        int n = rem / FF, k = rem % FF;
        val = Wkqv[(long)lt * FF * F3 + (long)k * F3 + n];
    } else {
        int j = idx - KQVW_ELEMS;
        int lt = j / (FF * FF);
        int rem = j - lt * (FF * FF);
        int n = rem / FF, k = rem % FF;
        val = Wout[(long)lt * FF * FF + (long)k * FF + n];
    }
    __nv_bfloat16 hi = __float2bfloat16_rn(val);
    __nv_bfloat16 lo = __float2bfloat16_rn(val - __bfloat162float(hi));
    g_wh[idx] = hi;
    g_wl[idx] = lo;
}

// split x0 into bf16 hi/lo planes (first layer only; later layers get planes
// written by the out-GEMM epilogue)
__global__ void splitx_kernel() {
    long i8 = ((long)blockIdx.x * blockDim.x + threadIdx.x) * 8;
    if (i8 >= (long)NTOT * FF) return;
    float v[8];
    *(float4*)&v[0] = *(const float4*)&g_x0[i8];
    *(float4*)&v[4] = *(const float4*)&g_x0[i8 + 4];
    __nv_bfloat16 h[8], l[8];
#pragma unroll
    for (int j = 0; j < 8; j++) {
        h[j] = __float2bfloat16_rn(v[j]);
        l[j] = __float2bfloat16_rn(v[j] - __bfloat162float(h[j]));
    }
    *(uint4*)&g_ah[i8] = *(const uint4*)&h[0];
    *(uint4*)&g_al[i8] = *(const uint4*)&l[0];
}

// ---------------- CSR build (once per launch) ----------------

__global__ void zero_deg_kernel() {
    int i = blockIdx.x * blockDim.x + threadIdx.x;
    if (i < NTOT) g_deg[i] = 0;
}

__global__ void hist_kernel(const int* __restrict__ dst, int E, int dt_off) {
    int e = blockIdx.x * blockDim.x + threadIdx.x;
    if (e < E) atomicAdd(&g_deg[dt_off + dst[e]], 1);
}

// single-block exclusive scan of g_deg -> g_off, g_cursor
__global__ void scan_kernel() {
    __shared__ int s[1024];
    int t = threadIdx.x;
    const int CHUNK = 79;            // 1024*79 = 80896 >= NTOT
    int base = t * CHUNK;
    int sum = 0;
    for (int i = 0; i < CHUNK; i++) {
        int idx = base + i;
        if (idx < NTOT) sum += g_deg[idx];
    }
    s[t] = sum;
    __syncthreads();
    for (int d = 1; d < 1024; d <<= 1) {
        int v = (t >= d) ? s[t - d] : 0;
        __syncthreads();
        s[t] += v;
        __syncthreads();
    }
    int run = (t == 0) ? 0 : s[t - 1];
    for (int i = 0; i < CHUNK; i++) {
        int idx = base + i;
        if (idx < NTOT) {
            g_off[idx] = run;
            g_cursor[idx] = run;
            run += g_deg[idx];
        }
    }
    if (t == 0) g_off[NTOT] = ETOT;
}

__global__ void scatter_kernel(const int* __restrict__ src,
                               const int* __restrict__ dst,
                               int E, int dt_off, int kroff, int r) {
    int e = blockIdx.x * blockDim.x + threadIdx.x;
    if (e >= E) return;
    int pos = atomicAdd(&g_cursor[dt_off + dst[e]], 1);
    g_csr[pos] = (r << 20) | (kroff + src[e]);
}

// ---------------- tensor-core GEMM ----------------
#define LDSM4(r, addr) \
    asm volatile("ldmatrix.sync.aligned.m8n8.x4.shared.b16 {%0,%1,%2,%3}, [%4];" \
        : "=r"((r)[0]), "=r"((r)[1]), "=r"((r)[2]), "=r"((r)[3]) : "r"(addr))

#define MMA16816(c, a0, a1, a2, a3, b0, b1) \
    asm volatile("mma.sync.aligned.m16n8k16.row.col.f32.bf16.bf16.f32 " \
        "{%0,%1,%2,%3}, {%4,%5,%6,%7}, {%8,%9}, {%0,%1,%2,%3};" \
        : "+f"((c)[0]), "+f"((c)[1]), "+f"((c)[2]), "+f"((c)[3]) \
        : "r"(a0), "r"(a1), "r"(a2), "r"(a3), "r"(b0), "r"(b1))

// epi==1: o -> s*o+(1-s)*x ; out = relu(.)+x
// xsplit==1 (epi only): also store result as bf16 hi/lo planes (next-layer x)
__global__ __launch_bounds__(256)
void mma_gemm(long a_row_off, long b_off, const float* __restrict__ bias,
              float* __restrict__ C,
              int M, int N, int epi, int xsplit,
              const float* __restrict__ X, const float* __restrict__ skipp) {
    __shared__ __align__(16) __nv_bfloat16 sAh[128 * BKPAD];
    __shared__ __align__(16) __nv_bfloat16 sAl[128 * BKPAD];
    __shared__ __align__(16) __nv_bfloat16 sBh[128 * BKPAD];
    __shared__ __align__(16) __nv_bfloat16 sBl[128 * BKPAD];

    int t = threadIdx.x;
    int bm = blockIdx.y * 128, bn = blockIdx.x * 128;
    int lane = t & 31, wid = t >> 5;
    int wm = (wid & 1) * 64, wn = (wid >> 1) * 32;

    float acc[4][4][4];
#pragma unroll
    for (int a = 0; a < 4; a++)
#pragma unroll
        for (int b = 0; b < 4; b++)
#pragma unroll
            for (int c = 0; c < 4; c++) acc[a][b][c] = 0.f;

    for (int kc = 0; kc < 128; kc += 32) {
#pragma unroll
        for (int i = 0; i < 4; i++) {
            int id = t + i * 256;
            int j = id & 3, m = (id >> 2) & 127, pl = id >> 9;
            const __nv_bfloat16* src = pl ? g_al : g_ah;
            __nv_bfloat16* dstS = pl ? sAl : sAh;
            uint4 v = make_uint4(0u, 0u, 0u, 0u);
            int gr = bm + m;
            if (gr < M)
                v = *(const uint4*)(src + (a_row_off + gr) * 128 + kc + j * 8);
            *(uint4*)(dstS + m * BKPAD + j * 8) = v;
        }
#pragma unroll
        for (int i = 0; i < 4; i++) {
            int id = t + i * 256;
            int j = id & 3, n = (id >> 2) & 127, pl = id >> 9;
            const __nv_bfloat16* src = pl ? g_wl : g_wh;
            __nv_bfloat16* dstS = pl ? sBl : sBh;
            uint4 v = *(const uint4*)(src + b_off + (long)(bn + n) * 128 + kc + j * 8);
            *(uint4*)(dstS + n * BKPAD + j * 8) = v;
        }
        __syncthreads();

#pragma unroll
        for (int k16 = 0; k16 < 32; k16 += 16) {
            unsigned af[4][2][4];
            int arow = wm + (lane & 15);
            int akoff = k16 + (lane >> 4) * 8;
#pragma unroll
            for (int mi = 0; mi < 4; mi++) {
                unsigned ah = (unsigned)__cvta_generic_to_shared(
                    sAh + (arow + mi * 16) * BKPAD + akoff);
                unsigned al = (unsigned)__cvta_generic_to_shared(
                    sAl + (arow + mi * 16) * BKPAD + akoff);
                LDSM4(af[mi][0], ah);
                LDSM4(af[mi][1], al);
            }
#pragma unroll
            for (int p = 0; p < 2; p++) {
                int nrow = wn + p * 16 + ((lane >> 4) & 1) * 8 + (lane & 7);
                int bkoff = k16 + ((lane >> 3) & 1) * 8;
                unsigned bh[4], bl[4];
                unsigned bha = (unsigned)__cvta_generic_to_shared(
                    sBh + nrow * BKPAD + bkoff);
                unsigned bla = (unsigned)__cvta_generic_to_shared(
                    sBl + nrow * BKPAD + bkoff);
                LDSM4(bh, bha);
                LDSM4(bl, bla);
#pragma unroll
                for (int mi = 0; mi < 4; mi++) {
                    MMA16816(acc[mi][2 * p], af[mi][0][0], af[mi][0][1], af[mi][0][2], af[mi][0][3], bh[0], bh[1]);
                    MMA16816(acc[mi][2 * p], af[mi][0][0], af[mi][0][1], af[mi][0][2], af[mi][0][3], bl[0], bl[1]);
                    MMA16816(acc[mi][2 * p], af[mi][1][0], af[mi][1][1], af[mi][1][2], af[mi][1][3], bh[0], bh[1]);
                    MMA16816(acc[mi][2 * p + 1], af[mi][0][0], af[mi][0][1], af[mi][0][2], af[mi][0][3], bh[2], bh[3]);
                    MMA16816(acc[mi][2 * p + 1], af[mi][0][0], af[mi][0][1], af[mi][0][2], af[mi][0][3], bl[2], bl[3]);
                    MMA16816(acc[mi][2 * p + 1], af[mi][1][0], af[mi][1][1], af[mi][1][2], af[mi][1][3], bh[2], bh[3]);
                }
            }
        }
        __syncthreads();
    }

    float s = 0.f, oms = 0.f;
    if (epi) {
        float sv = *skipp;
        s = 1.f / (1.f + expf(-sv));
        oms = 1.f - s;
    }
#pragma unroll
    for (int mi = 0; mi < 4; mi++) {
#pragma unroll
        for (int nj = 0; nj < 4; nj++) {
            int rbase = bm + wm + mi * 16 + (lane >> 2);
            int col = bn + wn + nj * 8 + (lane & 3) * 2;
            float2 b2 = *(const float2*)&bias[col];
#pragma unroll
            for (int h = 0; h < 2; h++) {
                int gr = rbase + h * 8;
                if (gr >= M) continue;
                float o0 = acc[mi][nj][h * 2 + 0] + b2.x;
                float o1 = acc[mi][nj][h * 2 + 1] + b2.y;
                if (!epi) {
                    *(float2*)&C[(long)gr * N + col] = make_float2(o0, o1);
                } else {
                    float2 xv = *(const float2*)&X[(long)gr * 128 + col];
                    float n0 = s * o0 + oms * xv.x;
                    float n1 = s * o1 + oms * xv.y;
                    float r0 = fmaxf(n0, 0.f) + xv.x;
                    float r1 = fmaxf(n1, 0.f) + xv.y;
                    *(float2*)&C[(long)gr * N + col] = make_float2(r0, r1);
                    if (xsplit) {
                        long pidx = (a_row_off + gr) * 128 + col;
                        __nv_bfloat16 h0 = __float2bfloat16_rn(r0);
                        __nv_bfloat16 h1 = __float2bfloat16_rn(r1);
                        __nv_bfloat16 l0 = __float2bfloat16_rn(r0 - __bfloat162float(h0));
                        __nv_bfloat16 l1 = __float2bfloat16_rn(r1 - __bfloat162float(h1));
                        __nv_bfloat162 hv; hv.x = h0; hv.y = h1;
                        __nv_bfloat162 lv; lv.x = l0; lv.y = l1;
                        *(__nv_bfloat162*)&g_ah[pidx] = hv;
                        *(__nv_bfloat162*)&g_al[pidx] = lv;
                    }
                }
            }
        }
    }
}

// ---------------- edge-phase kernels ----------------

// k_r/v_r transform, output fp16
__global__ __launch_bounds__(256)
void krvr_kernel(const float* __restrict__ Ak, const float* __restrict__ Av,
                 int l, int r, int st_off, int nsrc, int kroff) {
    __shared__ float sA[2][HH][DD][DD];
    int tid = threadIdx.x;
    const float* Akb = Ak + (long)(l * NREL + r) * HH * DD * DD;
    const float* Avb = Av + (long)(l * NREL + r) * HH * DD * DD;
    float* sflat = &sA[0][0][0][0];
    for (int i = tid; i < 2048; i += 256) {
        sflat[i] = Akb[i];
        sflat[2048 + i] = Avb[i];
    }
    __syncthreads();

    int half = tid >> 7;
    int h = (tid & 127) >> 4;
    int e = tid & 15;
    int n0 = blockIdx.x * 16;
    __half* dst = half ? g_vrh : g_krh;
    int kqv_off = half ? 256 : 0;

    for (int ni = 0; ni < 16; ni++) {
        int n = n0 + ni;
        if (n >= nsrc) break;
        const float* srcp = g_kqv + (long)(st_off + n) * F3 + kqv_off + h * DD;
        float acc = 0.f;
#pragma unroll
        for (int d = 0; d < DD; d++) acc += srcp[d] * sA[half][h][d][e];
        dst[(long)(kroff + n) * FF + h * DD + e] = __float2half_rn(acc);
    }
}

// one warp per destination node: full attention for all its in-edges.
// out = (sum_j ex_j * v_j) / (sum_j ex_j) ; then gelu + bf16 split to planes.
__global__ __launch_bounds__(256)
void edge_fused_kernel(const float* __restrict__ prel, int l) {
    int warp = (blockIdx.x * blockDim.x + threadIdx.x) >> 5;
    int lane = threadIdx.x & 31;
    if (warp >= NTOT) return;
    int o0 = g_off[warp], o1 = g_off[warp + 1];
    int h = lane >> 2;

    float4 q4 = *(const float4*)(g_kqv + (long)warp * F3 + FF + lane * 4);
    float prh[NREL];
#pragma unroll
    for (int r = 0; r < NREL; r++)
        prh[r] = prel[(l * NREL + r) * HH + h] * 0.25f;

    float a0 = 0.f, a1 = 0.f, a2 = 0.f, a3 = 0.f, denom = 0.f;
    for (int j = o0; j < o1; j++) {
        int cv = g_csr[j];
        int row = cv & 0xFFFFF;
        int r = cv >> 20;
        uint2 ku = *(const uint2*)(g_krh + (long)row * FF + lane * 4);
        float2 ka = __half22float2(*(__half2*)&ku.x);
        float2 kb = __half22float2(*(__half2*)&ku.y);
        float p = q4.x * ka.x + q4.y * ka.y + q4.z * kb.x + q4.w * kb.y;
        p += __shfl_xor_sync(0xFFFFFFFFu, p, 1);
        p += __shfl_xor_sync(0xFFFFFFFFu, p, 2);
        float ex = expf(p * prh[r]);
        uint2 vu = *(const uint2*)(g_vrh + (long)row * FF + lane * 4);
        float2 va = __half22float2(*(__half2*)&vu.x);
        float2 vb = __half22float2(*(__half2*)&vu.y);
        a0 += ex * va.x;
        a1 += ex * va.y;
        a2 += ex * vb.x;
        a3 += ex * vb.y;
        denom += ex;
    }
    float inv = (o1 > o0) ? 1.f / denom : 0.f;
    float o[4] = {gelu_f(a0 * inv), gelu_f(a1 * inv),
                  gelu_f(a2 * inv), gelu_f(a3 * inv)};
    __nv_bfloat16 hb[4], lb[4];
#pragma unroll
    for (int i = 0; i < 4; i++) {
        hb[i] = __float2bfloat16_rn(o[i]);
        lb[i] = __float2bfloat16_rn(o[i] - __bfloat162float(hb[i]));
    }
    long idx = (long)warp * FF + lane * 4;
    *(uint2*)&g_ah[idx] = *(const uint2*)hb;
    *(uint2*)&g_al[idx] = *(const uint2*)lb;
}

// ---------------- launch ----------------
extern "C" void kernel_launch(void* const* d_in, const int* in_sizes, int n_in,
                              void* d_out, int out_size) {
    const float* xg   = (const float*)d_in[0];
    const float* xd   = (const float*)d_in[1];
    const float* xr   = (const float*)d_in[2];
    const float* Wkqv = (const float*)d_in[3];
    const float* bkqv = (const float*)d_in[4];
    const float* Ak   = (const float*)d_in[5];
    const float* Av   = (const float*)d_in[6];
    const float* prel = (const float*)d_in[7];
    const float* Wout = (const float*)d_in[8];
    const float* bout = (const float*)d_in[9];
    const float* skip = (const float*)d_in[10];
    const int* ei[4] = {(const int*)d_in[11], (const int*)d_in[12],
                        (const int*)d_in[13], (const int*)d_in[14]};
    float* outp = (float*)d_out;

    const int NELEM_BLOCKS = (NTOT * FF + 255) / 256;
    const int SPLIT_BLOCKS = (NTOT * FF / 8 + 255) / 256;

    // device base pointers for selecting x buffers
    float* d_x0; cudaGetSymbolAddress((void**)&d_x0, g_x0);
    float* d_x1; cudaGetSymbolAddress((void**)&d_x1, g_x1);
    float* d_kqv; cudaGetSymbolAddress((void**)&d_kqv, g_kqv);

    copyin_kernel<<<NELEM_BLOCKS, 256>>>(xg, xd, xr);
    splitw_kernel<<<(WTOT + 255) / 256, 256>>>(Wkqv, Wout);

    // CSR build (edge structure is layer-invariant)
    zero_deg_kernel<<<(NTOT + 255) / 256, 256>>>();
    for (int r = 0; r < NREL; r++)
        hist_kernel<<<(h_ES[r] + 255) / 256, 256>>>(
            ei[r] + h_ES[r], h_ES[r], h_OFFS[h_DSTT[r]]);
    scan_kernel<<<1, 1024>>>();
    for (int r = 0; r < NREL; r++)
        scatter_kernel<<<(h_ES[r] + 255) / 256, 256>>>(
            ei[r], ei[r] + h_ES[r], h_ES[r],
            h_OFFS[h_DSTT[r]], h_KROFF[r], r);

    // planes = x0
    splitx_kernel<<<SPLIT_BLOCKS, 256>>>();

    for (int l = 0; l < NLAYER; l++) {
        float* xcur = (l == 0) ? d_x0 : d_x1;

        // 1) kqv = x @ Wkqv + bkqv (reads planes)
        for (int t = 0; t < NTYPE; t++) {
            dim3 grid(F3 / 128, (h_NS[t] + 127) / 128);
            mma_gemm<<<grid, 256>>>(
                (long)h_OFFS[t],
                (long)(l * NTYPE + t) * F3 * FF,
                bkqv + (long)(l * NTYPE + t) * F3,
                d_kqv + (long)h_OFFS[t] * F3,
                h_NS[t], F3, 0, 0, 0, 0);
        }

        // 2) relation-specific k_r, v_r (fp16)
        for (int r = 0; r < NREL; r++) {
            int st = h_SRCT[r];
            krvr_kernel<<<(h_NS[st] + 15) / 16, 256>>>(
                Ak, Av, l, r, h_OFFS[st], h_NS[st], h_KROFF[r]);
        }

        // 3) fused edge phase: logits+softmax+aggregate+gelu+split -> planes
        edge_fused_kernel<<<NTOT / 8, 256>>>(prel, l);

        // 4) out GEMM + skip-blend + relu + residual (+ next-layer planes)
        float* cdst = (l == 0) ? d_x1 : outp;
        int xs = (l == 0) ? 1 : 0;
        for (int t = 0; t < NTYPE; t++) {
            dim3 grid(FF / 128, (h_NS[t] + 127) / 128);
            mma_gemm<<<grid, 256>>>(
                (long)h_OFFS[t],
                (long)KQVW_ELEMS + (long)(l * NTYPE + t) * FF * FF,
                bout + (long)(l * NTYPE + t) * FF,
                cdst + (long)h_OFFS[t] * FF,
                h_NS[t], FF, 1, xs,
                xcur + (long)h_OFFS[t] * FF,
                skip + l * NTYPE + t);
        }
    }
    (void)in_sizes; (void)n_in; (void)out_size;
}

// round 9
// speedup vs baseline: 1.6157x; 1.3632x over previous
#include <cuda_runtime.h>
#include <cuda_bf16.h>
#include <cuda_fp16.h>
#include <math.h>

// ---------------- problem constants ----------------
#define HH 8
#define DD 16
#define FF 128
#define F3 384
#define NLAYER 2
#define NTYPE 3
#define NREL 4
#define NTOT 80000
#define KRTOT 120000
#define ETOT 600000
#define BKPAD 40           // smem k-stride in bf16 (80 bytes): conflict-free ldmatrix

// folded qkv weights: [L][T][5 segs][128 n][128 k]
#define W2SEG 16384
#define W2PER (5 * W2SEG)
#define W2TOT (NLAYER * NTYPE * W2PER)          // 491520
#define OUTW_ELEMS (NLAYER * NTYPE * FF * FF)   //  98304
#define WALL (W2TOT + OUTW_ELEMS)

// host-side metadata
static const int h_NS[3]    = {50000, 20000, 10000};
static const int h_OFFS[4]  = {0, 50000, 70000, 80000};
static const int h_ES[4]    = {300000, 150000, 100000, 50000};
static const int h_DSTT[4]  = {0, 1, 0, 1};
static const int h_KROFF[4] = {0, 50000, 100000, 110000};

// ---------------- device scratch ----------------
__device__ __align__(16) float g_x0[NTOT * FF];
__device__ __align__(16) float g_x1[NTOT * FF];
__device__ __align__(16) float g_q[NTOT * FF];
// fp16 gather buffers (L2-resident)
__device__ __align__(16) __half g_krh[KRTOT * FF];
__device__ __align__(16) __half g_vrh[KRTOT * FF];
// bf16x2 split planes for tensor-core GEMM
__device__ __align__(16) __nv_bfloat16 g_ah[NTOT * FF];
__device__ __align__(16) __nv_bfloat16 g_al[NTOT * FF];
__device__ __align__(16) __nv_bfloat16 g_wh[WALL];   // [folded qkv | out], k-major
__device__ __align__(16) __nv_bfloat16 g_wl[WALL];
__device__ float g_b2[NLAYER * NTYPE * 5 * FF];      // folded biases
// CSR over global destinations
__device__ int g_deg[NTOT];
__device__ int g_off[NTOT + 1];
__device__ int g_cursor[NTOT];
__device__ int g_csr[ETOT];      // (r << 20) | (kroff + src)

__device__ __forceinline__ float gelu_f(float x) {
    return 0.5f * x * (1.f + erff(x * 0.70710678118654752440f));
}

// ---------------- setup kernels ----------------

// inputs -> g_x0 + bf16 hi/lo planes in one pass
__global__ void copyin_split_kernel(const float* __restrict__ xg,
                                    const float* __restrict__ xd,
                                    const float* __restrict__ xr) {
    long i8 = ((long)blockIdx.x * blockDim.x + threadIdx.x) * 8;
    if (i8 >= (long)NTOT * FF) return;
    const long n1 = 50000L * FF, n2 = 70000L * FF;
    const float* src;
    long off;
    if (i8 < n1)      { src = xg; off = i8; }
    else if (i8 < n2) { src = xd; off = i8 - n1; }
    else              { src = xr; off = i8 - n2; }
    float v[8];
    *(float4*)&v[0] = *(const float4*)&src[off];
    *(float4*)&v[4] = *(const float4*)&src[off + 4];
    *(float4*)&g_x0[i8]     = *(const float4*)&v[0];
    *(float4*)&g_x0[i8 + 4] = *(const float4*)&v[4];
    __nv_bfloat16 h[8], l[8];
#pragma unroll
    for (int j = 0; j < 8; j++) {
        h[j] = __float2bfloat16_rn(v[j]);
        l[j] = __float2bfloat16_rn(v[j] - __bfloat162float(h[j]));
    }
    *(uint4*)&g_ah[i8] = *(const uint4*)&h[0];
    *(uint4*)&g_al[i8] = *(const uint4*)&l[0];
}

// fold Ak/Av into Wkqv: per (l,t) produce [q | k_rA | k_rB | v_rA | v_rB]
// stored k-major, split into bf16 hi/lo planes.
__global__ void fold_kernel(const float* __restrict__ Wkqv,
                            const float* __restrict__ Ak,
                            const float* __restrict__ Av) {
    int idx = blockIdx.x * blockDim.x + threadIdx.x;
    if (idx >= W2TOT) return;
    int k = idx & 127;
    int n = (idx >> 7) & 127;
    int sl = idx >> 14;           // lt*5 + seg
    int seg = sl % 5, lt = sl / 5;
    int l = lt / NTYPE, t = lt % NTYPE;
    const float* W = Wkqv + (long)lt * FF * F3;
    float val = 0.f;
    if (seg == 0) {
        val = W[(long)k * F3 + FF + n];
    } else if (t != 1) {
        int r = (t == 0 ? 0 : 2) + ((seg == 2 || seg == 4) ? 1 : 0);
        int h = n >> 4, e = n & 15;
        const float* A = ((seg <= 2) ? Ak : Av) +
                         ((long)(l * NREL + r) * HH + h) * DD * DD;
        int colbase = (seg <= 2 ? 0 : 2 * FF) + h * DD;
#pragma unroll
        for (int d = 0; d < DD; d++)
            val += W[(long)k * F3 + colbase + d] * A[d * DD + e];
    }
    __nv_bfloat16 hi = __float2bfloat16_rn(val);
    g_wh[idx] = hi;
    g_wl[idx] = __float2bfloat16_rn(val - __bfloat162float(hi));
}

__global__ void foldb_kernel(const float* __restrict__ bkqv,
                             const float* __restrict__ Ak,
                             const float* __restrict__ Av) {
    int idx = blockIdx.x * blockDim.x + threadIdx.x;
    if (idx >= NLAYER * NTYPE * 5 * FF) return;
    int n = idx & 127;
    int sl = idx >> 7;
    int seg = sl % 5, lt = sl / 5;
    int l = lt / NTYPE, t = lt % NTYPE;
    const float* b = bkqv + (long)lt * F3;
    float val = 0.f;
    if (seg == 0) {
        val = b[FF + n];
    } else if (t != 1) {
        int r = (t == 0 ? 0 : 2) + ((seg == 2 || seg == 4) ? 1 : 0);
        int h = n >> 4, e = n & 15;
        const float* A = ((seg <= 2) ? Ak : Av) +
                         ((long)(l * NREL + r) * HH + h) * DD * DD;
        int colbase = (seg <= 2 ? 0 : 2 * FF) + h * DD;
#pragma unroll
        for (int d = 0; d < DD; d++)
            val += b[colbase + d] * A[d * DD + e];
    }
    g_b2[idx] = val;
}

// out weights, transposed k-major, split
__global__ void splitw_kernel(const float* __restrict__ Wout) {
    int idx = blockIdx.x * blockDim.x + threadIdx.x;
    if (idx >= OUTW_ELEMS) return;
    int lt = idx / (FF * FF);
    int rem = idx - lt * (FF * FF);
    int n = rem / FF, k = rem % FF;
    float val = Wout[(long)lt * FF * FF + (long)k * FF + n];
    __nv_bfloat16 hi = __float2bfloat16_rn(val);
    g_wh[W2TOT + idx] = hi;
    g_wl[W2TOT + idx] = __float2bfloat16_rn(val - __bfloat162float(hi));
}

// ---------------- CSR build ----------------

__global__ void zero_deg_kernel() {
    int i = blockIdx.x * blockDim.x + threadIdx.x;
    if (i < NTOT) g_deg[i] = 0;
}

__global__ void hist_kernel(const int* __restrict__ dst, int E, int dt_off) {
    int e = blockIdx.x * blockDim.x + threadIdx.x;
    if (e < E) atomicAdd(&g_deg[dt_off + dst[e]], 1);
}

__global__ void scan_kernel() {
    __shared__ int s[1024];
    int t = threadIdx.x;
    const int CHUNK = 79;
    int base = t * CHUNK;
    int sum = 0;
    for (int i = 0; i < CHUNK; i++) {
        int idx = base + i;
        if (idx < NTOT) sum += g_deg[idx];
    }
    s[t] = sum;
    __syncthreads();
    for (int d = 1; d < 1024; d <<= 1) {
        int v = (t >= d) ? s[t - d] : 0;
        __syncthreads();
        s[t] += v;
        __syncthreads();
    }
    int run = (t == 0) ? 0 : s[t - 1];
    for (int i = 0; i < CHUNK; i++) {
        int idx = base + i;
        if (idx < NTOT) {
            g_off[idx] = run;
            g_cursor[idx] = run;
            run += g_deg[idx];
        }
    }
    if (t == 0) g_off[NTOT] = ETOT;
}

__global__ void scatter_kernel(const int* __restrict__ src,
                               const int* __restrict__ dst,
                               int E, int dt_off, int kroff, int r) {
    int e = blockIdx.x * blockDim.x + threadIdx.x;
    if (e >= E) return;
    int pos = atomicAdd(&g_cursor[dt_off + dst[e]], 1);
    g_csr[pos] = (r << 20) | (kroff + src[e]);
}

// ---------------- tensor-core GEMM ----------------
#define LDSM4(r, addr) \
    asm volatile("ldmatrix.sync.aligned.m8n8.x4.shared.b16 {%0,%1,%2,%3}, [%4];" \
        : "=r"((r)[0]), "=r"((r)[1]), "=r"((r)[2]), "=r"((r)[3]) : "r"(addr))

#define MMA16816(c, a0, a1, a2, a3, b0, b1) \
    asm volatile("mma.sync.aligned.m16n8k16.row.col.f32.bf16.bf16.f32 " \
        "{%0,%1,%2,%3}, {%4,%5,%6,%7}, {%8,%9}, {%0,%1,%2,%3};" \
        : "+f"((c)[0]), "+f"((c)[1]), "+f"((c)[2]), "+f"((c)[3]) \
        : "r"(a0), "r"(a1), "r"(a2), "r"(a3), "r"(b0), "r"(b1))

// mode 0: plain C store
// mode 1: epi (skip-blend + relu + residual); xsplit also writes bf16 planes
// mode 2: qkv routing: seg0 -> g_q fp32; seg1/2 -> g_krh; seg3/4 -> g_vrh (fp16)
__global__ __launch_bounds__(256)
void mma_gemm(long a_row_off, long b_off, const float* __restrict__ bias,
              float* __restrict__ C,
              int M, int N, int mode, int xsplit,
              long kroffA, long kroffB,
              const float* __restrict__ X, const float* __restrict__ skipp) {
    __shared__ __align__(16) __nv_bfloat16 sAh[128 * BKPAD];
    __shared__ __align__(16) __nv_bfloat16 sAl[128 * BKPAD];
    __shared__ __align__(16) __nv_bfloat16 sBh[128 * BKPAD];
    __shared__ __align__(16) __nv_bfloat16 sBl[128 * BKPAD];

    int t = threadIdx.x;
    int bm = blockIdx.y * 128, bn = blockIdx.x * 128;
    int lane = t & 31, wid = t >> 5;
    int wm = (wid & 1) * 64, wn = (wid >> 1) * 32;

    float acc[4][4][4];
#pragma unroll
    for (int a = 0; a < 4; a++)
#pragma unroll
        for (int b = 0; b < 4; b++)
#pragma unroll
            for (int c = 0; c < 4; c++) acc[a][b][c] = 0.f;

    for (int kc = 0; kc < 128; kc += 32) {
#pragma unroll
        for (int i = 0; i < 4; i++) {
            int id = t + i * 256;
            int j = id & 3, m = (id >> 2) & 127, pl = id >> 9;
            const __nv_bfloat16* src = pl ? g_al : g_ah;
            __nv_bfloat16* dstS = pl ? sAl : sAh;
            uint4 v = make_uint4(0u, 0u, 0u, 0u);
            int gr = bm + m;
            if (gr < M)
                v = *(const uint4*)(src + (a_row_off + gr) * 128 + kc + j * 8);
            *(uint4*)(dstS + m * BKPAD + j * 8) = v;
        }
#pragma unroll
        for (int i = 0; i < 4; i++) {
            int id = t + i * 256;
            int j = id & 3, n = (id >> 2) & 127, pl = id >> 9;
            const __nv_bfloat16* src = pl ? g_wl : g_wh;
            __nv_bfloat16* dstS = pl ? sBl : sBh;
            uint4 v = *(const uint4*)(src + b_off + (long)(bn + n) * 128 + kc + j * 8);
            *(uint4*)(dstS + n * BKPAD + j * 8) = v;
        }
        __syncthreads();

#pragma unroll
        for (int k16 = 0; k16 < 32; k16 += 16) {
            unsigned af[4][2][4];
            int arow = wm + (lane & 15);
            int akoff = k16 + (lane >> 4) * 8;
#pragma unroll
            for (int mi = 0; mi < 4; mi++) {
                unsigned ah = (unsigned)__cvta_generic_to_shared(
                    sAh + (arow + mi * 16) * BKPAD + akoff);
                unsigned al = (unsigned)__cvta_generic_to_shared(
                    sAl + (arow + mi * 16) * BKPAD + akoff);
                LDSM4(af[mi][0], ah);
                LDSM4(af[mi][1], al);
            }
#pragma unroll
            for (int p = 0; p < 2; p++) {
                int nrow = wn + p * 16 + ((lane >> 4) & 1) * 8 + (lane & 7);
                int bkoff = k16 + ((lane >> 3) & 1) * 8;
                unsigned bh[4], bl[4];
                unsigned bha = (unsigned)__cvta_generic_to_shared(
                    sBh + nrow * BKPAD + bkoff);
                unsigned bla = (unsigned)__cvta_generic_to_shared(
                    sBl + nrow * BKPAD + bkoff);
                LDSM4(bh, bha);
                LDSM4(bl, bla);
#pragma unroll
                for (int mi = 0; mi < 4; mi++) {
                    MMA16816(acc[mi][2 * p], af[mi][0][0], af[mi][0][1], af[mi][0][2], af[mi][0][3], bh[0], bh[1]);
                    MMA16816(acc[mi][2 * p], af[mi][0][0], af[mi][0][1], af[mi][0][2], af[mi][0][3], bl[0], bl[1]);
                    MMA16816(acc[mi][2 * p], af[mi][1][0], af[mi][1][1], af[mi][1][2], af[mi][1][3], bh[0], bh[1]);
                    MMA16816(acc[mi][2 * p + 1], af[mi][0][0], af[mi][0][1], af[mi][0][2], af[mi][0][3], bh[2], bh[3]);
                    MMA16816(acc[mi][2 * p + 1], af[mi][0][0], af[mi][0][1], af[mi][0][2], af[mi][0][3], bl[2], bl[3]);
                    MMA16816(acc[mi][2 * p + 1], af[mi][1][0], af[mi][1][1], af[mi][1][2], af[mi][1][3], bh[2], bh[3]);
                }
            }
        }
        __syncthreads();
    }

    float s = 0.f, oms = 0.f;
    if (mode == 1) {
        float sv = *skipp;
        s = 1.f / (1.f + expf(-sv));
        oms = 1.f - s;
    }
#pragma unroll
    for (int mi = 0; mi < 4; mi++) {
#pragma unroll
        for (int nj = 0; nj < 4; nj++) {
            int rbase = bm + wm + mi * 16 + (lane >> 2);
            int col = bn + wn + nj * 8 + (lane & 3) * 2;
            float2 b2 = *(const float2*)&bias[col];
#pragma unroll
            for (int h = 0; h < 2; h++) {
                int gr = rbase + h * 8;
                if (gr >= M) continue;
                float o0 = acc[mi][nj][h * 2 + 0] + b2.x;
                float o1 = acc[mi][nj][h * 2 + 1] + b2.y;
                if (mode == 0) {
                    *(float2*)&C[(long)gr * N + col] = make_float2(o0, o1);
                } else if (mode == 2) {
                    int seg = col >> 7, cc = col & 127;
                    if (seg == 0) {
                        *(float2*)&g_q[(a_row_off + gr) * 128 + cc] =
                            make_float2(o0, o1);
                    } else {
                        __half2 hv = __floats2half2_rn(o0, o1);
                        long roff = ((seg == 1 || seg == 3) ? kroffA : kroffB) + gr;
                        if (seg <= 2)
                            *(__half2*)&g_krh[roff * 128 + cc] = hv;
                        else
                            *(__half2*)&g_vrh[roff * 128 + cc] = hv;
                    }
                } else {
                    float2 xv = *(const float2*)&X[(long)gr * 128 + col];
                    float n0 = s * o0 + oms * xv.x;
                    float n1 = s * o1 + oms * xv.y;
                    float r0 = fmaxf(n0, 0.f) + xv.x;
                    float r1 = fmaxf(n1, 0.f) + xv.y;
                    *(float2*)&C[(long)gr * N + col] = make_float2(r0, r1);
                    if (xsplit) {
                        long pidx = (a_row_off + gr) * 128 + col;
                        __nv_bfloat16 h0 = __float2bfloat16_rn(r0);
                        __nv_bfloat16 h1 = __float2bfloat16_rn(r1);
                        __nv_bfloat16 l0 = __float2bfloat16_rn(r0 - __bfloat162float(h0));
                        __nv_bfloat16 l1 = __float2bfloat16_rn(r1 - __bfloat162float(h1));
                        __nv_bfloat162 hv; hv.x = h0; hv.y = h1;
                        __nv_bfloat162 lv; lv.x = l0; lv.y = l1;
                        *(__nv_bfloat162*)&g_ah[pidx] = hv;
                        *(__nv_bfloat162*)&g_al[pidx] = lv;
                    }
                }
            }
        }
    }
}

// ---------------- fused edge phase ----------------
// one warp per destination node: logits + softmax + aggregate + gelu + split
__global__ __launch_bounds__(256)
void edge_fused_kernel(const float* __restrict__ prel, int l) {
    int warp = (blockIdx.x * blockDim.x + threadIdx.x) >> 5;
    int lane = threadIdx.x & 31;
    if (warp >= NTOT) return;
    int o0 = g_off[warp], o1 = g_off[warp + 1];
    int h = lane >> 2;

    float4 q4 = *(const float4*)(g_q + (long)warp * FF + lane * 4);
    float prh[NREL];
#pragma unroll
    for (int r = 0; r < NREL; r++)
        prh[r] = prel[(l * NREL + r) * HH + h] * 0.25f;

    float a0 = 0.f, a1 = 0.f, a2 = 0.f, a3 = 0.f, denom = 0.f;
#pragma unroll 2
    for (int j = o0; j < o1; j++) {
        int cv = g_csr[j];
        int row = cv & 0xFFFFF;
        int r = cv >> 20;
        uint2 ku = *(const uint2*)(g_krh + (long)row * FF + lane * 4);
        float2 ka = __half22float2(*(__half2*)&ku.x);
        float2 kb = __half22float2(*(__half2*)&ku.y);
        float p = q4.x * ka.x + q4.y * ka.y + q4.z * kb.x + q4.w * kb.y;
        p += __shfl_xor_sync(0xFFFFFFFFu, p, 1);
        p += __shfl_xor_sync(0xFFFFFFFFu, p, 2);
        float ex = expf(p * prh[r]);
        uint2 vu = *(const uint2*)(g_vrh + (long)row * FF + lane * 4);
        float2 va = __half22float2(*(__half2*)&vu.x);
        float2 vb = __half22float2(*(__half2*)&vu.y);
        a0 += ex * va.x;
        a1 += ex * va.y;
        a2 += ex * vb.x;
        a3 += ex * vb.y;
        denom += ex;
    }
    float inv = (o1 > o0) ? 1.f / denom : 0.f;
    float o[4] = {gelu_f(a0 * inv), gelu_f(a1 * inv),
                  gelu_f(a2 * inv), gelu_f(a3 * inv)};
    __nv_bfloat16 hb[4], lb[4];
#pragma unroll
    for (int i = 0; i < 4; i++) {
        hb[i] = __float2bfloat16_rn(o[i]);
        lb[i] = __float2bfloat16_rn(o[i] - __bfloat162float(hb[i]));
    }
    long idx = (long)warp * FF + lane * 4;
    *(uint2*)&g_ah[idx] = *(const uint2*)hb;
    *(uint2*)&g_al[idx] = *(const uint2*)lb;
}

// ---------------- launch ----------------
extern "C" void kernel_launch(void* const* d_in, const int* in_sizes, int n_in,
                              void* d_out, int out_size) {
    const float* xg   = (const float*)d_in[0];
    const float* xd   = (const float*)d_in[1];
    const float* xr   = (const float*)d_in[2];
    const float* Wkqv = (const float*)d_in[3];
    const float* bkqv = (const float*)d_in[4];
    const float* Ak   = (const float*)d_in[5];
    const float* Av   = (const float*)d_in[6];
    const float* prel = (const float*)d_in[7];
    const float* Wout = (const float*)d_in[8];
    const float* bout = (const float*)d_in[9];
    const float* skip = (const float*)d_in[10];
    const int* ei[4] = {(const int*)d_in[11], (const int*)d_in[12],
                        (const int*)d_in[13], (const int*)d_in[14]};
    float* outp = (float*)d_out;

    const int SPLIT_BLOCKS = (NTOT * FF / 8 + 255) / 256;

    float* d_x0; cudaGetSymbolAddress((void**)&d_x0, g_x0);
    float* d_x1; cudaGetSymbolAddress((void**)&d_x1, g_x1);
    float* d_b2; cudaGetSymbolAddress((void**)&d_b2, g_b2);

    copyin_split_kernel<<<SPLIT_BLOCKS, 256>>>(xg, xd, xr);
    fold_kernel<<<(W2TOT + 255) / 256, 256>>>(Wkqv, Ak, Av);
    foldb_kernel<<<(NLAYER * NTYPE * 5 * FF + 255) / 256, 256>>>(bkqv, Ak, Av);
    splitw_kernel<<<(OUTW_ELEMS + 255) / 256, 256>>>(Wout);

    // CSR build (edge structure is layer-invariant)
    zero_deg_kernel<<<(NTOT + 255) / 256, 256>>>();
    for (int r = 0; r < NREL; r++)
        hist_kernel<<<(h_ES[r] + 255) / 256, 256>>>(
            ei[r] + h_ES[r], h_ES[r], h_OFFS[h_DSTT[r]]);
    scan_kernel<<<1, 1024>>>();
    for (int r = 0; r < NREL; r++)
        scatter_kernel<<<(h_ES[r] + 255) / 256, 256>>>(
            ei[r], ei[r] + h_ES[r], h_ES[r],
            h_OFFS[h_DSTT[r]], h_KROFF[r], r);

    for (int l = 0; l < NLAYER; l++) {
        float* xcur = (l == 0) ? d_x0 : d_x1;

        // 1) fused qkv GEMM: q + folded k_r/v_r per source type
        for (int t = 0; t < NTYPE; t++) {
            int N = (t == 1) ? 128 : 640;
            long kroffA = (t == 0) ? h_KROFF[0] : h_KROFF[2];
            long kroffB = (t == 0) ? h_KROFF[1] : h_KROFF[3];
            dim3 grid(N / 128, (h_NS[t] + 127) / 128);
            mma_gemm<<<grid, 256>>>(
                (long)h_OFFS[t],
                (long)(l * NTYPE + t) * W2PER,
                d_b2 + (long)(l * NTYPE + t) * 5 * FF,
                0, h_NS[t], N, 2, 0,
                kroffA, kroffB, 0, 0);
        }

        // 2) fused edge phase -> planes
        edge_fused_kernel<<<NTOT / 8, 256>>>(prel, l);

        // 3) out GEMM + skip-blend + relu + residual (+ next-layer planes)
        float* cdst = (l == 0) ? d_x1 : outp;
        int xs = (l == 0) ? 1 : 0;
        for (int t = 0; t < NTYPE; t++) {
            dim3 grid(1, (h_NS[t] + 127) / 128);
            mma_gemm<<<grid, 256>>>(
                (long)h_OFFS[t],
                (long)W2TOT + (long)(l * NTYPE + t) * FF * FF,
                bout + (long)(l * NTYPE + t) * FF,
                cdst + (long)h_OFFS[t] * FF,
                h_NS[t], FF, 1, xs,
                0, 0,
                xcur + (long)h_OFFS[t] * FF,
                skip + l * NTYPE + t);
        }
    }
    (void)in_sizes; (void)n_in; (void)out_size;
}

// round 10
// speedup vs baseline: 1.8381x; 1.1376x over previous
#include <cuda_runtime.h>
#include <cuda_bf16.h>
#include <cuda_fp16.h>
#include <math.h>

// ---------------- problem constants ----------------
#define HH 8
#define DD 16
#define FF 128
#define F3 384
#define NLAYER 2
#define NTYPE 3
#define NREL 4
#define NTOT 80000
#define KRTOT 120000
#define ETOT 600000
#define BKPAD 40           // smem k-stride in bf16 (80 bytes): conflict-free ldmatrix
#define PLANE (128 * BKPAD)            // 5120 elems
#define GEMM_SMEM (2 * 4 * PLANE * 2)  // bytes: 2 buffers x 4 planes x bf16

// folded qkv weights: [L][T][5 segs][128 n][128 k]
#define W2SEG 16384
#define W2PER (5 * W2SEG)
#define W2TOT (NLAYER * NTYPE * W2PER)          // 491520
#define OUTW_ELEMS (NLAYER * NTYPE * FF * FF)   //  98304
#define WALL (W2TOT + OUTW_ELEMS)

// host-side metadata
static const int h_NS[3]    = {50000, 20000, 10000};
static const int h_OFFS[4]  = {0, 50000, 70000, 80000};
static const int h_ES[4]    = {300000, 150000, 100000, 50000};
static const int h_DSTT[4]  = {0, 1, 0, 1};
static const int h_KROFF[4] = {0, 50000, 100000, 110000};

// ---------------- device scratch ----------------
__device__ __align__(16) float g_x0[NTOT * FF];
__device__ __align__(16) float g_x1[NTOT * FF];
__device__ __align__(16) float g_q[NTOT * FF];
// fp16 gather buffers (L2-resident)
__device__ __align__(16) __half g_krh[KRTOT * FF];
__device__ __align__(16) __half g_vrh[KRTOT * FF];
// bf16x2 split planes for tensor-core GEMM
__device__ __align__(16) __nv_bfloat16 g_ah[NTOT * FF];
__device__ __align__(16) __nv_bfloat16 g_al[NTOT * FF];
__device__ __align__(16) __nv_bfloat16 g_wh[WALL];   // [folded qkv | out], k-major
__device__ __align__(16) __nv_bfloat16 g_wl[WALL];
__device__ float g_b2[NLAYER * NTYPE * 5 * FF];      // folded biases
// CSR over global destinations
__device__ int g_deg[NTOT];
__device__ int g_off[NTOT + 1];
__device__ int g_cursor[NTOT];
__device__ int g_csr[ETOT];      // (r << 20) | (kroff + src)

__device__ __forceinline__ float gelu_f(float x) {
    return 0.5f * x * (1.f + erff(x * 0.70710678118654752440f));
}

// ---------------- setup kernels ----------------

__global__ void copyin_split_kernel(const float* __restrict__ xg,
                                    const float* __restrict__ xd,
                                    const float* __restrict__ xr) {
    long i8 = ((long)blockIdx.x * blockDim.x + threadIdx.x) * 8;
    if (i8 >= (long)NTOT * FF) return;
    const long n1 = 50000L * FF, n2 = 70000L * FF;
    const float* src;
    long off;
    if (i8 < n1)      { src = xg; off = i8; }
    else if (i8 < n2) { src = xd; off = i8 - n1; }
    else              { src = xr; off = i8 - n2; }
    float v[8];
    *(float4*)&v[0] = *(const float4*)&src[off];
    *(float4*)&v[4] = *(const float4*)&src[off + 4];
    *(float4*)&g_x0[i8]     = *(const float4*)&v[0];
    *(float4*)&g_x0[i8 + 4] = *(const float4*)&v[4];
    __nv_bfloat16 h[8], l[8];
#pragma unroll
    for (int j = 0; j < 8; j++) {
        h[j] = __float2bfloat16_rn(v[j]);
        l[j] = __float2bfloat16_rn(v[j] - __bfloat162float(h[j]));
    }
    *(uint4*)&g_ah[i8] = *(const uint4*)&h[0];
    *(uint4*)&g_al[i8] = *(const uint4*)&l[0];
}

// fold Ak/Av into Wkqv: per (l,t) produce [q | k_rA | k_rB | v_rA | v_rB]
__global__ void fold_kernel(const float* __restrict__ Wkqv,
                            const float* __restrict__ Ak,
                            const float* __restrict__ Av) {
    int idx = blockIdx.x * blockDim.x + threadIdx.x;
    if (idx >= W2TOT) return;
    int k = idx & 127;
    int n = (idx >> 7) & 127;
    int sl = idx >> 14;
    int seg = sl % 5, lt = sl / 5;
    int l = lt / NTYPE, t = lt % NTYPE;
    const float* W = Wkqv + (long)lt * FF * F3;
    float val = 0.f;
    if (seg == 0) {
        val = W[(long)k * F3 + FF + n];
    } else if (t != 1) {
        int r = (t == 0 ? 0 : 2) + ((seg == 2 || seg == 4) ? 1 : 0);
        int h = n >> 4, e = n & 15;
        const float* A = ((seg <= 2) ? Ak : Av) +
                         ((long)(l * NREL + r) * HH + h) * DD * DD;
        int colbase = (seg <= 2 ? 0 : 2 * FF) + h * DD;
#pragma unroll
        for (int d = 0; d < DD; d++)
            val += W[(long)k * F3 + colbase + d] * A[d * DD + e];
    }
    __nv_bfloat16 hi = __float2bfloat16_rn(val);
    g_wh[idx] = hi;
    g_wl[idx] = __float2bfloat16_rn(val - __bfloat162float(hi));
}

__global__ void foldb_kernel(const float* __restrict__ bkqv,
                             const float* __restrict__ Ak,
                             const float* __restrict__ Av) {
    int idx = blockIdx.x * blockDim.x + threadIdx.x;
    if (idx >= NLAYER * NTYPE * 5 * FF) return;
    int n = idx & 127;
    int sl = idx >> 7;
    int seg = sl % 5, lt = sl / 5;
    int l = lt / NTYPE, t = lt % NTYPE;
    const float* b = bkqv + (long)lt * F3;
    float val = 0.f;
    if (seg == 0) {
        val = b[FF + n];
    } else if (t != 1) {
        int r = (t == 0 ? 0 : 2) + ((seg == 2 || seg == 4) ? 1 : 0);
        int h = n >> 4, e = n & 15;
        const float* A = ((seg <= 2) ? Ak : Av) +
                         ((long)(l * NREL + r) * HH + h) * DD * DD;
        int colbase = (seg <= 2 ? 0 : 2 * FF) + h * DD;
#pragma unroll
        for (int d = 0; d < DD; d++)
            val += b[colbase + d] * A[d * DD + e];
    }
    g_b2[idx] = val;
}

__global__ void splitw_kernel(const float* __restrict__ Wout) {
    int idx = blockIdx.x * blockDim.x + threadIdx.x;
    if (idx >= OUTW_ELEMS) return;
    int lt = idx / (FF * FF);
    int rem = idx - lt * (FF * FF);
    int n = rem / FF, k = rem % FF;
    float val = Wout[(long)lt * FF * FF + (long)k * FF + n];
    __nv_bfloat16 hi = __float2bfloat16_rn(val);
    g_wh[W2TOT + idx] = hi;
    g_wl[W2TOT + idx] = __float2bfloat16_rn(val - __bfloat162float(hi));
}

// ---------------- CSR build ----------------

__global__ void zero_deg_kernel() {
    int i = blockIdx.x * blockDim.x + threadIdx.x;
    if (i < NTOT) g_deg[i] = 0;
}

__global__ void hist_kernel(const int* __restrict__ dst, int E, int dt_off) {
    int e = blockIdx.x * blockDim.x + threadIdx.x;
    if (e < E) atomicAdd(&g_deg[dt_off + dst[e]], 1);
}

__global__ void scan_kernel() {
    __shared__ int s[1024];
    int t = threadIdx.x;
    const int CHUNK = 79;
    int base = t * CHUNK;
    int sum = 0;
    for (int i = 0; i < CHUNK; i++) {
        int idx = base + i;
        if (idx < NTOT) sum += g_deg[idx];
    }
    s[t] = sum;
    __syncthreads();
    for (int d = 1; d < 1024; d <<= 1) {
        int v = (t >= d) ? s[t - d] : 0;
        __syncthreads();
        s[t] += v;
        __syncthreads();
    }
    int run = (t == 0) ? 0 : s[t - 1];
    for (int i = 0; i < CHUNK; i++) {
        int idx = base + i;
        if (idx < NTOT) {
            g_off[idx] = run;
            g_cursor[idx] = run;
            run += g_deg[idx];
        }
    }
    if (t == 0) g_off[NTOT] = ETOT;
}

__global__ void scatter_kernel(const int* __restrict__ src,
                               const int* __restrict__ dst,
                               int E, int dt_off, int kroff, int r) {
    int e = blockIdx.x * blockDim.x + threadIdx.x;
    if (e >= E) return;
    int pos = atomicAdd(&g_cursor[dt_off + dst[e]], 1);
    g_csr[pos] = (r << 20) | (kroff + src[e]);
}

// ---------------- tensor-core GEMM (cp.async double-buffered) ----------------
#define LDSM4(r, addr) \
    asm volatile("ldmatrix.sync.aligned.m8n8.x4.shared.b16 {%0,%1,%2,%3}, [%4];" \
        : "=r"((r)[0]), "=r"((r)[1]), "=r"((r)[2]), "=r"((r)[3]) : "r"(addr))

#define MMA16816(c, a0, a1, a2, a3, b0, b1) \
    asm volatile("mma.sync.aligned.m16n8k16.row.col.f32.bf16.bf16.f32 " \
        "{%0,%1,%2,%3}, {%4,%5,%6,%7}, {%8,%9}, {%0,%1,%2,%3};" \
        : "+f"((c)[0]), "+f"((c)[1]), "+f"((c)[2]), "+f"((c)[3]) \
        : "r"(a0), "r"(a1), "r"(a2), "r"(a3), "r"(b0), "r"(b1))

__device__ __forceinline__ void cp16(__nv_bfloat16* dst, const __nv_bfloat16* src,
                                     int srcsize) {
    unsigned d = (unsigned)__cvta_generic_to_shared(dst);
    asm volatile("cp.async.ca.shared.global [%0], [%1], 16, %2;"
                 :: "r"(d), "l"(src), "r"(srcsize));
}
#define CP_COMMIT() asm volatile("cp.async.commit_group;")
#define CP_WAIT(n)  asm volatile("cp.async.wait_group %0;" :: "n"(n))

// mode 0: plain C store
// mode 1: epi (skip-blend + relu + residual); xsplit also writes bf16 planes
// mode 2: qkv routing: seg0 -> g_q fp32; seg1/2 -> g_krh; seg3/4 -> g_vrh (fp16)
__global__ __launch_bounds__(256)
void mma_gemm(long a_row_off, long b_off, const float* __restrict__ bias,
              float* __restrict__ C,
              int M, int N, int mode, int xsplit,
              long kroffA, long kroffB,
              const float* __restrict__ X, const float* __restrict__ skipp) {
    extern __shared__ __align__(16) __nv_bfloat16 smem[];

    int t = threadIdx.x;
    int bm = blockIdx.y * 128, bn = blockIdx.x * 128;
    int lane = t & 31, wid = t >> 5;
    int wm = (wid & 1) * 64, wn = (wid >> 1) * 32;

    float acc[4][4][4];
#pragma unroll
    for (int a = 0; a < 4; a++)
#pragma unroll
        for (int b = 0; b < 4; b++)
#pragma unroll
            for (int c = 0; c < 4; c++) acc[a][b][c] = 0.f;

    // per-thread load coordinates (same for every chunk)
    int jA = t & 3, mA = (t >> 2) & 63;          // 2 rows per thread per plane? no:
    // loader mapping: 1024 16B-transfers per (A or B) chunk = 4 per thread
    // id = t + i*256 ; j = id&3 (16B group), row = (id>>2)&127, pl = id>>9

    auto load_chunk = [&](int kc, int buf) {
        __nv_bfloat16* base = smem + buf * 4 * PLANE;
#pragma unroll
        for (int i = 0; i < 4; i++) {
            int id = t + i * 256;
            int j = id & 3, m = (id >> 2) & 127, pl = id >> 9;
            const __nv_bfloat16* srcA = pl ? g_al : g_ah;
            __nv_bfloat16* dstA = base + pl * PLANE + m * BKPAD + j * 8;
            int gr = bm + m;
            const __nv_bfloat16* sa = srcA + (a_row_off + gr) * 128 + kc + j * 8;
            cp16(dstA, sa, (gr < M) ? 16 : 0);
        }
#pragma unroll
        for (int i = 0; i < 4; i++) {
            int id = t + i * 256;
            int j = id & 3, n = (id >> 2) & 127, pl = id >> 9;
            const __nv_bfloat16* srcB = pl ? g_wl : g_wh;
            __nv_bfloat16* dstB = base + (2 + pl) * PLANE + n * BKPAD + j * 8;
            cp16(dstB, srcB + b_off + (long)(bn + n) * 128 + kc + j * 8, 16);
        }
    };

    load_chunk(0, 0);
    CP_COMMIT();

    for (int ci = 0; ci < 4; ci++) {
        if (ci < 3) {
            load_chunk((ci + 1) * 32, (ci + 1) & 1);
            CP_COMMIT();
            CP_WAIT(1);
        } else {
            CP_WAIT(0);
        }
        __syncthreads();

        const __nv_bfloat16* buf = smem + (ci & 1) * 4 * PLANE;
        const __nv_bfloat16* sAh = buf;
        const __nv_bfloat16* sAl = buf + PLANE;
        const __nv_bfloat16* sBh = buf + 2 * PLANE;
        const __nv_bfloat16* sBl = buf + 3 * PLANE;

#pragma unroll
        for (int k16 = 0; k16 < 32; k16 += 16) {
            unsigned af[4][2][4];
            int arow = wm + (lane & 15);
            int akoff = k16 + (lane >> 4) * 8;
#pragma unroll
            for (int mi = 0; mi < 4; mi++) {
                unsigned ah = (unsigned)__cvta_generic_to_shared(
                    sAh + (arow + mi * 16) * BKPAD + akoff);
                unsigned al = (unsigned)__cvta_generic_to_shared(
                    sAl + (arow + mi * 16) * BKPAD + akoff);
                LDSM4(af[mi][0], ah);
                LDSM4(af[mi][1], al);
            }
#pragma unroll
            for (int p = 0; p < 2; p++) {
                int nrow = wn + p * 16 + ((lane >> 4) & 1) * 8 + (lane & 7);
                int bkoff = k16 + ((lane >> 3) & 1) * 8;
                unsigned bh[4], bl[4];
                unsigned bha = (unsigned)__cvta_generic_to_shared(
                    sBh + nrow * BKPAD + bkoff);
                unsigned bla = (unsigned)__cvta_generic_to_shared(
                    sBl + nrow * BKPAD + bkoff);
                LDSM4(bh, bha);
                LDSM4(bl, bla);
#pragma unroll
                for (int mi = 0; mi < 4; mi++) {
                    MMA16816(acc[mi][2 * p], af[mi][0][0], af[mi][0][1], af[mi][0][2], af[mi][0][3], bh[0], bh[1]);
                    MMA16816(acc[mi][2 * p], af[mi][0][0], af[mi][0][1], af[mi][0][2], af[mi][0][3], bl[0], bl[1]);
                    MMA16816(acc[mi][2 * p], af[mi][1][0], af[mi][1][1], af[mi][1][2], af[mi][1][3], bh[0], bh[1]);
                    MMA16816(acc[mi][2 * p + 1], af[mi][0][0], af[mi][0][1], af[mi][0][2], af[mi][0][3], bh[2], bh[3]);
                    MMA16816(acc[mi][2 * p + 1], af[mi][0][0], af[mi][0][1], af[mi][0][2], af[mi][0][3], bl[2], bl[3]);
                    MMA16816(acc[mi][2 * p + 1], af[mi][1][0], af[mi][1][1], af[mi][1][2], af[mi][1][3], bh[2], bh[3]);
                }
            }
        }
        __syncthreads();
    }

    float s = 0.f, oms = 0.f;
    if (mode == 1) {
        float sv = *skipp;
        s = 1.f / (1.f + expf(-sv));
        oms = 1.f - s;
    }
#pragma unroll
    for (int mi = 0; mi < 4; mi++) {
#pragma unroll
        for (int nj = 0; nj < 4; nj++) {
            int rbase = bm + wm + mi * 16 + (lane >> 2);
            int col = bn + wn + nj * 8 + (lane & 3) * 2;
            float2 b2 = *(const float2*)&bias[col];
#pragma unroll
            for (int h = 0; h < 2; h++) {
                int gr = rbase + h * 8;
                if (gr >= M) continue;
                float o0 = acc[mi][nj][h * 2 + 0] + b2.x;
                float o1 = acc[mi][nj][h * 2 + 1] + b2.y;
                if (mode == 0) {
                    *(float2*)&C[(long)gr * N + col] = make_float2(o0, o1);
                } else if (mode == 2) {
                    int seg = col >> 7, cc = col & 127;
                    if (seg == 0) {
                        *(float2*)&g_q[(a_row_off + gr) * 128 + cc] =
                            make_float2(o0, o1);
                    } else {
                        __half2 hv = __floats2half2_rn(o0, o1);
                        long roff = ((seg == 1 || seg == 3) ? kroffA : kroffB) + gr;
                        if (seg <= 2)
                            *(__half2*)&g_krh[roff * 128 + cc] = hv;
                        else
                            *(__half2*)&g_vrh[roff * 128 + cc] = hv;
                    }
                } else {
                    float2 xv = *(const float2*)&X[(long)gr * 128 + col];
                    float n0 = s * o0 + oms * xv.x;
                    float n1 = s * o1 + oms * xv.y;
                    float r0 = fmaxf(n0, 0.f) + xv.x;
                    float r1 = fmaxf(n1, 0.f) + xv.y;
                    *(float2*)&C[(long)gr * N + col] = make_float2(r0, r1);
                    if (xsplit) {
                        long pidx = (a_row_off + gr) * 128 + col;
                        __nv_bfloat16 h0 = __float2bfloat16_rn(r0);
                        __nv_bfloat16 h1 = __float2bfloat16_rn(r1);
                        __nv_bfloat16 l0 = __float2bfloat16_rn(r0 - __bfloat162float(h0));
                        __nv_bfloat16 l1 = __float2bfloat16_rn(r1 - __bfloat162float(h1));
                        __nv_bfloat162 hv; hv.x = h0; hv.y = h1;
                        __nv_bfloat162 lv; lv.x = l0; lv.y = l1;
                        *(__nv_bfloat162*)&g_ah[pidx] = hv;
                        *(__nv_bfloat162*)&g_al[pidx] = lv;
                    }
                }
            }
        }
    }
}

// ---------------- fused edge phase (2-edge ILP) ----------------
__global__ __launch_bounds__(256)
void edge_fused_kernel(const float* __restrict__ prel, int l) {
    int warp = (blockIdx.x * blockDim.x + threadIdx.x) >> 5;
    int lane = threadIdx.x & 31;
    if (warp >= NTOT) return;
    int o0 = g_off[warp], o1 = g_off[warp + 1];
    int h = lane >> 2;

    float4 q4 = *(const float4*)(g_q + (long)warp * FF + lane * 4);
    float prh[NREL];
#pragma unroll
    for (int r = 0; r < NREL; r++)
        prh[r] = prel[(l * NREL + r) * HH + h] * 0.25f;

    float a0 = 0.f, a1 = 0.f, a2 = 0.f, a3 = 0.f, denom = 0.f;
    int j = o0;
    for (; j + 1 < o1; j += 2) {
        int cv0 = g_csr[j], cv1 = g_csr[j + 1];
        long r0 = (long)(cv0 & 0xFFFFF) * FF + lane * 4;
        long r1 = (long)(cv1 & 0xFFFFF) * FF + lane * 4;
        int rel0 = cv0 >> 20, rel1 = cv1 >> 20;
        // issue all four gathers up front
        uint2 ku0 = *(const uint2*)(g_krh + r0);
        uint2 ku1 = *(const uint2*)(g_krh + r1);
        uint2 vu0 = *(const uint2*)(g_vrh + r0);
        uint2 vu1 = *(const uint2*)(g_vrh + r1);
        float2 ka0 = __half22float2(*(__half2*)&ku0.x);
        float2 kb0 = __half22float2(*(__half2*)&ku0.y);
        float2 ka1 = __half22float2(*(__half2*)&ku1.x);
        float2 kb1 = __half22float2(*(__half2*)&ku1.y);
        float p0 = q4.x * ka0.x + q4.y * ka0.y + q4.z * kb0.x + q4.w * kb0.y;
        float p1 = q4.x * ka1.x + q4.y * ka1.y + q4.z * kb1.x + q4.w * kb1.y;
        p0 += __shfl_xor_sync(0xFFFFFFFFu, p0, 1);
        p1 += __shfl_xor_sync(0xFFFFFFFFu, p1, 1);
        p0 += __shfl_xor_sync(0xFFFFFFFFu, p0, 2);
        p1 += __shfl_xor_sync(0xFFFFFFFFu, p1, 2);
        float ex0 = __expf(p0 * prh[rel0]);
        float ex1 = __expf(p1 * prh[rel1]);
        float2 va0 = __half22float2(*(__half2*)&vu0.x);
        float2 vb0 = __half22float2(*(__half2*)&vu0.y);
        float2 va1 = __half22float2(*(__half2*)&vu1.x);
        float2 vb1 = __half22float2(*(__half2*)&vu1.y);
        a0 += ex0 * va0.x + ex1 * va1.x;
        a1 += ex0 * va0.y + ex1 * va1.y;
        a2 += ex0 * vb0.x + ex1 * vb1.x;
        a3 += ex0 * vb0.y + ex1 * vb1.y;
        denom += ex0 + ex1;
    }
    if (j < o1) {
        int cv = g_csr[j];
        long r0 = (long)(cv & 0xFFFFF) * FF + lane * 4;
        int rel = cv >> 20;
        uint2 ku = *(const uint2*)(g_krh + r0);
        uint2 vu = *(const uint2*)(g_vrh + r0);
        float2 ka = __half22float2(*(__half2*)&ku.x);
        float2 kb = __half22float2(*(__half2*)&ku.y);
        float p = q4.x * ka.x + q4.y * ka.y + q4.z * kb.x + q4.w * kb.y;
        p += __shfl_xor_sync(0xFFFFFFFFu, p, 1);
        p += __shfl_xor_sync(0xFFFFFFFFu, p, 2);
        float ex = __expf(p * prh[rel]);
        float2 va = __half22float2(*(__half2*)&vu.x);
        float2 vb = __half22float2(*(__half2*)&vu.y);
        a0 += ex * va.x;
        a1 += ex * va.y;
        a2 += ex * vb.x;
        a3 += ex * vb.y;
        denom += ex;
    }
    float inv = (o1 > o0) ? 1.f / denom : 0.f;
    float o[4] = {gelu_f(a0 * inv), gelu_f(a1 * inv),
                  gelu_f(a2 * inv), gelu_f(a3 * inv)};
    __nv_bfloat16 hb[4], lb[4];
#pragma unroll
    for (int i = 0; i < 4; i++) {
        hb[i] = __float2bfloat16_rn(o[i]);
        lb[i] = __float2bfloat16_rn(o[i] - __bfloat162float(hb[i]));
    }
    long idx = (long)warp * FF + lane * 4;
    *(uint2*)&g_ah[idx] = *(const uint2*)hb;
    *(uint2*)&g_al[idx] = *(const uint2*)lb;
}

// ---------------- launch ----------------
extern "C" void kernel_launch(void* const* d_in, const int* in_sizes, int n_in,
                              void* d_out, int out_size) {
    const float* xg   = (const float*)d_in[0];
    const float* xd   = (const float*)d_in[1];
    const float* xr   = (const float*)d_in[2];
    const float* Wkqv = (const float*)d_in[3];
    const float* bkqv = (const float*)d_in[4];
    const float* Ak   = (const float*)d_in[5];
    const float* Av   = (const float*)d_in[6];
    const float* prel = (const float*)d_in[7];
    const float* Wout = (const float*)d_in[8];
    const float* bout = (const float*)d_in[9];
    const float* skip = (const float*)d_in[10];
    const int* ei[4] = {(const int*)d_in[11], (const int*)d_in[12],
                        (const int*)d_in[13], (const int*)d_in[14]};
    float* outp = (float*)d_out;

    const int SPLIT_BLOCKS = (NTOT * FF / 8 + 255) / 256;

    float* d_x0; cudaGetSymbolAddress((void**)&d_x0, g_x0);
    float* d_x1; cudaGetSymbolAddress((void**)&d_x1, g_x1);
    float* d_b2; cudaGetSymbolAddress((void**)&d_b2, g_b2);

    cudaFuncSetAttribute(mma_gemm, cudaFuncAttributeMaxDynamicSharedMemorySize,
                         GEMM_SMEM);

    copyin_split_kernel<<<SPLIT_BLOCKS, 256>>>(xg, xd, xr);
    fold_kernel<<<(W2TOT + 255) / 256, 256>>>(Wkqv, Ak, Av);
    foldb_kernel<<<(NLAYER * NTYPE * 5 * FF + 255) / 256, 256>>>(bkqv, Ak, Av);
    splitw_kernel<<<(OUTW_ELEMS + 255) / 256, 256>>>(Wout);

    // CSR build (edge structure is layer-invariant)
    zero_deg_kernel<<<(NTOT + 255) / 256, 256>>>();
    for (int r = 0; r < NREL; r++)
        hist_kernel<<<(h_ES[r] + 255) / 256, 256>>>(
            ei[r] + h_ES[r], h_ES[r], h_OFFS[h_DSTT[r]]);
    scan_kernel<<<1, 1024>>>();
    for (int r = 0; r < NREL; r++)
        scatter_kernel<<<(h_ES[r] + 255) / 256, 256>>>(
            ei[r], ei[r] + h_ES[r], h_ES[r],
            h_OFFS[h_DSTT[r]], h_KROFF[r], r);

    for (int l = 0; l < NLAYER; l++) {
        float* xcur = (l == 0) ? d_x0 : d_x1;

        // 1) fused qkv GEMM: q + folded k_r/v_r per source type
        for (int t = 0; t < NTYPE; t++) {
            int N = (t == 1) ? 128 : 640;
            long kroffA = (t == 0) ? h_KROFF[0] : h_KROFF[2];
            long kroffB = (t == 0) ? h_KROFF[1] : h_KROFF[3];
            dim3 grid(N / 128, (h_NS[t] + 127) / 128);
            mma_gemm<<<grid, 256, GEMM_SMEM>>>(
                (long)h_OFFS[t],
                (long)(l * NTYPE + t) * W2PER,
                d_b2 + (long)(l * NTYPE + t) * 5 * FF,
                0, h_NS[t], N, 2, 0,
                kroffA, kroffB, 0, 0);
        }

        // 2) fused edge phase -> planes
        edge_fused_kernel<<<NTOT / 8, 256>>>(prel, l);

        // 3) out GEMM + skip-blend + relu + residual (+ next-layer planes)
        float* cdst = (l == 0) ? d_x1 : outp;
        int xs = (l == 0) ? 1 : 0;
        for (int t = 0; t < NTYPE; t++) {
            dim3 grid(1, (h_NS[t] + 127) / 128);
            mma_gemm<<<grid, 256, GEMM_SMEM>>>(
                (long)h_OFFS[t],
                (long)W2TOT + (long)(l * NTYPE + t) * FF * FF,
                bout + (long)(l * NTYPE + t) * FF,
                cdst + (long)h_OFFS[t] * FF,
                h_NS[t], FF, 1, xs,
                0, 0,
                xcur + (long)h_OFFS[t] * FF,
                skip + l * NTYPE + t);
        }
    }
    (void)in_sizes; (void)n_in; (void)out_size;
}

// round 11
// speedup vs baseline: 1.8491x; 1.0060x over previous
#include <cuda_runtime.h>
#include <cuda_bf16.h>
#include <cuda_fp16.h>
#include <math.h>

// ---------------- problem constants ----------------
#define HH 8
#define DD 16
#define FF 128
#define F3 384
#define NLAYER 2
#define NTYPE 3
#define NREL 4
#define NTOT 80000
#define KRTOT 120000
#define ETOT 600000
#define BKPAD 40           // smem k-stride in bf16 (80 bytes): conflict-free ldmatrix
#define PLANE (128 * BKPAD)            // 5120 elems
#define GEMM_SMEM (2 * 4 * PLANE * 2)  // bytes

// folded qkv weights: [L][T][5 segs][128 n][128 k]
#define W2SEG 16384
#define W2PER (5 * W2SEG)
#define W2TOT (NLAYER * NTYPE * W2PER)          // 491520
#define OUTW_ELEMS (NLAYER * NTYPE * FF * FF)   //  98304
#define WALL (W2TOT + OUTW_ELEMS)

// block-mapping constants
#define MT0 391
#define MT1 157
#define MT2 79
#define QKV_B0 (5 * MT0)
#define QKV_B1 MT1
#define QKV_BLOCKS (QKV_B0 + QKV_B1 + 5 * MT2)   // 2507
#define OUT_BLOCKS (MT0 + MT1 + MT2)             // 627

// host-side metadata
static const int h_ES[4] = {300000, 150000, 100000, 50000};

// ---------------- device scratch ----------------
__device__ __align__(16) float g_x0[NTOT * FF];
__device__ __align__(16) float g_x1[NTOT * FF];
__device__ __align__(16) float g_q[NTOT * FF];
__device__ __align__(16) __half g_krh[KRTOT * FF];
__device__ __align__(16) __half g_vrh[KRTOT * FF];
__device__ __align__(16) __nv_bfloat16 g_ah[NTOT * FF];
__device__ __align__(16) __nv_bfloat16 g_al[NTOT * FF];
__device__ __align__(16) __nv_bfloat16 g_wh[WALL];
__device__ __align__(16) __nv_bfloat16 g_wl[WALL];
__device__ float g_b2[NLAYER * NTYPE * 5 * FF];
__device__ int g_deg[NTOT];
__device__ int g_off[NTOT + 1];
__device__ int g_cursor[NTOT];
__device__ int g_csr[ETOT];      // (r << 20) | (kroff + src)

__device__ __forceinline__ float gelu_f(float x) {
    return 0.5f * x * (1.f + erff(x * 0.70710678118654752440f));
}

// ---------------- setup kernels ----------------

__global__ void copyin_split_kernel(const float* __restrict__ xg,
                                    const float* __restrict__ xd,
                                    const float* __restrict__ xr) {
    long i8 = ((long)blockIdx.x * blockDim.x + threadIdx.x) * 8;
    if (i8 >= (long)NTOT * FF) return;
    const long n1 = 50000L * FF, n2 = 70000L * FF;
    const float* src;
    long off;
    if (i8 < n1)      { src = xg; off = i8; }
    else if (i8 < n2) { src = xd; off = i8 - n1; }
    else              { src = xr; off = i8 - n2; }
    float v[8];
    *(float4*)&v[0] = *(const float4*)&src[off];
    *(float4*)&v[4] = *(const float4*)&src[off + 4];
    *(float4*)&g_x0[i8]     = *(const float4*)&v[0];
    *(float4*)&g_x0[i8 + 4] = *(const float4*)&v[4];
    __nv_bfloat16 h[8], l[8];
#pragma unroll
    for (int j = 0; j < 8; j++) {
        h[j] = __float2bfloat16_rn(v[j]);
        l[j] = __float2bfloat16_rn(v[j] - __bfloat162float(h[j]));
    }
    *(uint4*)&g_ah[i8] = *(const uint4*)&h[0];
    *(uint4*)&g_al[i8] = *(const uint4*)&l[0];
}

__global__ void fold_kernel(const float* __restrict__ Wkqv,
                            const float* __restrict__ Ak,
                            const float* __restrict__ Av) {
    int idx = blockIdx.x * blockDim.x + threadIdx.x;
    if (idx >= W2TOT) return;
    int k = idx & 127;
    int n = (idx >> 7) & 127;
    int sl = idx >> 14;
    int seg = sl % 5, lt = sl / 5;
    int l = lt / NTYPE, t = lt % NTYPE;
    const float* W = Wkqv + (long)lt * FF * F3;
    float val = 0.f;
    if (seg == 0) {
        val = W[(long)k * F3 + FF + n];
    } else if (t != 1) {
        int r = (t == 0 ? 0 : 2) + ((seg == 2 || seg == 4) ? 1 : 0);
        int h = n >> 4, e = n & 15;
        const float* A = ((seg <= 2) ? Ak : Av) +
                         ((long)(l * NREL + r) * HH + h) * DD * DD;
        int colbase = (seg <= 2 ? 0 : 2 * FF) + h * DD;
#pragma unroll
        for (int d = 0; d < DD; d++)
            val += W[(long)k * F3 + colbase + d] * A[d * DD + e];
    }
    __nv_bfloat16 hi = __float2bfloat16_rn(val);
    g_wh[idx] = hi;
    g_wl[idx] = __float2bfloat16_rn(val - __bfloat162float(hi));
}

__global__ void foldb_kernel(const float* __restrict__ bkqv,
                             const float* __restrict__ Ak,
                             const float* __restrict__ Av) {
    int idx = blockIdx.x * blockDim.x + threadIdx.x;
    if (idx >= NLAYER * NTYPE * 5 * FF) return;
    int n = idx & 127;
    int sl = idx >> 7;
    int seg = sl % 5, lt = sl / 5;
    int l = lt / NTYPE, t = lt % NTYPE;
    const float* b = bkqv + (long)lt * F3;
    float val = 0.f;
    if (seg == 0) {
        val = b[FF + n];
    } else if (t != 1) {
        int r = (t == 0 ? 0 : 2) + ((seg == 2 || seg == 4) ? 1 : 0);
        int h = n >> 4, e = n & 15;
        const float* A = ((seg <= 2) ? Ak : Av) +
                         ((long)(l * NREL + r) * HH + h) * DD * DD;
        int colbase = (seg <= 2 ? 0 : 2 * FF) + h * DD;
#pragma unroll
        for (int d = 0; d < DD; d++)
            val += b[colbase + d] * A[d * DD + e];
    }
    g_b2[idx] = val;
}

__global__ void splitw_kernel(const float* __restrict__ Wout) {
    int idx = blockIdx.x * blockDim.x + threadIdx.x;
    if (idx >= OUTW_ELEMS) return;
    int lt = idx / (FF * FF);
    int rem = idx - lt * (FF * FF);
    int n = rem / FF, k = rem % FF;
    float val = Wout[(long)lt * FF * FF + (long)k * FF + n];
    __nv_bfloat16 hi = __float2bfloat16_rn(val);
    g_wh[W2TOT + idx] = hi;
    g_wl[W2TOT + idx] = __float2bfloat16_rn(val - __bfloat162float(hi));
}

// ---------------- CSR build (fused over relations) ----------------

__global__ void zero_deg_kernel() {
    int i = blockIdx.x * blockDim.x + threadIdx.x;
    if (i < NTOT) g_deg[i] = 0;
}

__device__ __forceinline__ void edge_decode(int e, const int* e0, const int* e1,
                                            const int* e2, const int* e3,
                                            int& r, int& off, const int*& ep,
                                            int& E, int& dt_off, int& kroff) {
    if (e < 300000)      { r = 0; off = e;          ep = e0; E = 300000; dt_off = 0;     kroff = 0; }
    else if (e < 450000) { r = 1; off = e - 300000; ep = e1; E = 150000; dt_off = 50000; kroff = 50000; }
    else if (e < 550000) { r = 2; off = e - 450000; ep = e2; E = 100000; dt_off = 0;     kroff = 100000; }
    else                 { r = 3; off = e - 550000; ep = e3; E = 50000;  dt_off = 50000; kroff = 110000; }
}

__global__ void hist_all_kernel(const int* __restrict__ e0, const int* __restrict__ e1,
                                const int* __restrict__ e2, const int* __restrict__ e3) {
    int e = blockIdx.x * blockDim.x + threadIdx.x;
    if (e >= ETOT) return;
    int r, off, E, dt_off, kroff;
    const int* ep;
    edge_decode(e, e0, e1, e2, e3, r, off, ep, E, dt_off, kroff);
    atomicAdd(&g_deg[dt_off + ep[E + off]], 1);
}

__global__ void scan_kernel() {
    __shared__ int s[1024];
    int t = threadIdx.x;
    const int CHUNK = 79;
    int base = t * CHUNK;
    int sum = 0;
    for (int i = 0; i < CHUNK; i++) {
        int idx = base + i;
        if (idx < NTOT) sum += g_deg[idx];
    }
    s[t] = sum;
    __syncthreads();
    for (int d = 1; d < 1024; d <<= 1) {
        int v = (t >= d) ? s[t - d] : 0;
        __syncthreads();
        s[t] += v;
        __syncthreads();
    }
    int run = (t == 0) ? 0 : s[t - 1];
    for (int i = 0; i < CHUNK; i++) {
        int idx = base + i;
        if (idx < NTOT) {
            g_off[idx] = run;
            g_cursor[idx] = run;
            run += g_deg[idx];
        }
    }
    if (t == 0) g_off[NTOT] = ETOT;
}

__global__ void scatter_all_kernel(const int* __restrict__ e0, const int* __restrict__ e1,
                                   const int* __restrict__ e2, const int* __restrict__ e3) {
    int e = blockIdx.x * blockDim.x + threadIdx.x;
    if (e >= ETOT) return;
    int r, off, E, dt_off, kroff;
    const int* ep;
    edge_decode(e, e0, e1, e2, e3, r, off, ep, E, dt_off, kroff);
    int pos = atomicAdd(&g_cursor[dt_off + ep[E + off]], 1);
    g_csr[pos] = (r << 20) | (kroff + ep[off]);
}

// ---------------- tensor-core GEMM core ----------------
#define LDSM4(r, addr) \
    asm volatile("ldmatrix.sync.aligned.m8n8.x4.shared.b16 {%0,%1,%2,%3}, [%4];" \
        : "=r"((r)[0]), "=r"((r)[1]), "=r"((r)[2]), "=r"((r)[3]) : "r"(addr))

#define MMA16816(c, a0, a1, a2, a3, b0, b1) \
    asm volatile("mma.sync.aligned.m16n8k16.row.col.f32.bf16.bf16.f32 " \
        "{%0,%1,%2,%3}, {%4,%5,%6,%7}, {%8,%9}, {%0,%1,%2,%3};" \
        : "+f"((c)[0]), "+f"((c)[1]), "+f"((c)[2]), "+f"((c)[3]) \
        : "r"(a0), "r"(a1), "r"(a2), "r"(a3), "r"(b0), "r"(b1))

__device__ __forceinline__ void cp16(__nv_bfloat16* dst, const __nv_bfloat16* src,
                                     int srcsize) {
    unsigned d = (unsigned)__cvta_generic_to_shared(dst);
    asm volatile("cp.async.ca.shared.global [%0], [%1], 16, %2;"
                 :: "r"(d), "l"(src), "r"(srcsize));
}
#define CP_COMMIT() asm volatile("cp.async.commit_group;")
#define CP_WAIT(n)  asm volatile("cp.async.wait_group %0;" :: "n"(n))

__device__ __forceinline__ void gemm_core(long a_row_off, long b_off,
                                          int bm, int bn, int M,
                                          __nv_bfloat16* smem,
                                          float acc[4][4][4]) {
    int t = threadIdx.x;
    int lane = t & 31, wid = t >> 5;
    int wm = (wid & 1) * 64, wn = (wid >> 1) * 32;

#pragma unroll
    for (int a = 0; a < 4; a++)
#pragma unroll
        for (int b = 0; b < 4; b++)
#pragma unroll
            for (int c = 0; c < 4; c++) acc[a][b][c] = 0.f;

#pragma unroll 1
    for (int pre = 0; pre < 1; pre++) {  // initial load, chunk 0
#pragma unroll
        for (int i = 0; i < 4; i++) {
            int id = t + i * 256;
            int j = id & 3, m = (id >> 2) & 127, pl = id >> 9;
            const __nv_bfloat16* srcA = pl ? g_al : g_ah;
            int gr = bm + m;
            cp16(smem + pl * PLANE + m * BKPAD + j * 8,
                 srcA + (a_row_off + gr) * 128 + j * 8, (gr < M) ? 16 : 0);
        }
#pragma unroll
        for (int i = 0; i < 4; i++) {
            int id = t + i * 256;
            int j = id & 3, n = (id >> 2) & 127, pl = id >> 9;
            const __nv_bfloat16* srcB = pl ? g_wl : g_wh;
            cp16(smem + (2 + pl) * PLANE + n * BKPAD + j * 8,
                 srcB + b_off + (long)(bn + n) * 128 + j * 8, 16);
        }
        CP_COMMIT();
    }

    for (int ci = 0; ci < 4; ci++) {
        if (ci < 3) {
            int kc = (ci + 1) * 32;
            __nv_bfloat16* nb = smem + ((ci + 1) & 1) * 4 * PLANE;
#pragma unroll
            for (int i = 0; i < 4; i++) {
                int id = t + i * 256;
                int j = id & 3, m = (id >> 2) & 127, pl = id >> 9;
                const __nv_bfloat16* srcA = pl ? g_al : g_ah;
                int gr = bm + m;
                cp16(nb + pl * PLANE + m * BKPAD + j * 8,
                     srcA + (a_row_off + gr) * 128 + kc + j * 8, (gr < M) ? 16 : 0);
            }
#pragma unroll
            for (int i = 0; i < 4; i++) {
                int id = t + i * 256;
                int j = id & 3, n = (id >> 2) & 127, pl = id >> 9;
                const __nv_bfloat16* srcB = pl ? g_wl : g_wh;
                cp16(nb + (2 + pl) * PLANE + n * BKPAD + j * 8,
                     srcB + b_off + (long)(bn + n) * 128 + kc + j * 8, 16);
            }
            CP_COMMIT();
            CP_WAIT(1);
        } else {
            CP_WAIT(0);
        }
        __syncthreads();

        const __nv_bfloat16* buf = smem + (ci & 1) * 4 * PLANE;
        const __nv_bfloat16* sAh = buf;
        const __nv_bfloat16* sAl = buf + PLANE;
        const __nv_bfloat16* sBh = buf + 2 * PLANE;
        const __nv_bfloat16* sBl = buf + 3 * PLANE;

#pragma unroll
        for (int k16 = 0; k16 < 32; k16 += 16) {
            unsigned af[4][2][4];
            int arow = wm + (lane & 15);
            int akoff = k16 + (lane >> 4) * 8;
#pragma unroll
            for (int mi = 0; mi < 4; mi++) {
                unsigned ah = (unsigned)__cvta_generic_to_shared(
                    sAh + (arow + mi * 16) * BKPAD + akoff);
                unsigned al = (unsigned)__cvta_generic_to_shared(
                    sAl + (arow + mi * 16) * BKPAD + akoff);
                LDSM4(af[mi][0], ah);
                LDSM4(af[mi][1], al);
            }
#pragma unroll
            for (int p = 0; p < 2; p++) {
                int nrow = wn + p * 16 + ((lane >> 4) & 1) * 8 + (lane & 7);
                int bkoff = k16 + ((lane >> 3) & 1) * 8;
                unsigned bh[4], bl[4];
                LDSM4(bh, (unsigned)__cvta_generic_to_shared(sBh + nrow * BKPAD + bkoff));
                LDSM4(bl, (unsigned)__cvta_generic_to_shared(sBl + nrow * BKPAD + bkoff));
#pragma unroll
                for (int mi = 0; mi < 4; mi++) {
                    MMA16816(acc[mi][2 * p], af[mi][0][0], af[mi][0][1], af[mi][0][2], af[mi][0][3], bh[0], bh[1]);
                    MMA16816(acc[mi][2 * p], af[mi][0][0], af[mi][0][1], af[mi][0][2], af[mi][0][3], bl[0], bl[1]);
                    MMA16816(acc[mi][2 * p], af[mi][1][0], af[mi][1][1], af[mi][1][2], af[mi][1][3], bh[0], bh[1]);
                    MMA16816(acc[mi][2 * p + 1], af[mi][0][0], af[mi][0][1], af[mi][0][2], af[mi][0][3], bh[2], bh[3]);
                    MMA16816(acc[mi][2 * p + 1], af[mi][0][0], af[mi][0][1], af[mi][0][2], af[mi][0][3], bl[2], bl[3]);
                    MMA16816(acc[mi][2 * p + 1], af[mi][1][0], af[mi][1][1], af[mi][1][2], af[mi][1][3], bh[2], bh[3]);
                }
            }
        }
        __syncthreads();
    }
}

// combined qkv GEMM: one launch covers all 3 types
__global__ __launch_bounds__(256)
void mma_qkv_kernel(int l) {
    extern __shared__ __align__(16) __nv_bfloat16 smem[];
    int bid = blockIdx.x;
    int t, nt, mt;
    if (bid < QKV_B0)                { t = 0; nt = bid % 5; mt = bid / 5; }
    else if (bid < QKV_B0 + QKV_B1)  { t = 1; nt = 0; mt = bid - QKV_B0; }
    else { int b = bid - QKV_B0 - QKV_B1; t = 2; nt = b % 5; mt = b / 5; }

    int M = (t == 0) ? 50000 : (t == 1 ? 20000 : 10000);
    long offs = (t == 0) ? 0 : (t == 1 ? 50000 : 70000);
    long kroffA = (t == 0) ? 0 : 100000;
    long kroffB = (t == 0) ? 50000 : 110000;
    int bm = mt * 128, bn = nt * 128;
    int lt = l * NTYPE + t;

    float acc[4][4][4];
    gemm_core(offs, (long)lt * W2PER, bm, bn, M, smem, acc);

    int lane = threadIdx.x & 31, wid = threadIdx.x >> 5;
    int wm = (wid & 1) * 64, wn = (wid >> 1) * 32;
    const float* bias = g_b2 + (long)lt * 5 * FF;
#pragma unroll
    for (int mi = 0; mi < 4; mi++) {
#pragma unroll
        for (int nj = 0; nj < 4; nj++) {
            int rbase = bm + wm + mi * 16 + (lane >> 2);
            int col = bn + wn + nj * 8 + (lane & 3) * 2;
            float2 b2 = *(const float2*)&bias[col];
#pragma unroll
            for (int h = 0; h < 2; h++) {
                int gr = rbase + h * 8;
                if (gr >= M) continue;
                float o0 = acc[mi][nj][h * 2 + 0] + b2.x;
                float o1 = acc[mi][nj][h * 2 + 1] + b2.y;
                int seg = col >> 7, cc = col & 127;
                if (seg == 0) {
                    *(float2*)&g_q[(offs + gr) * 128 + cc] = make_float2(o0, o1);
                } else {
                    __half2 hv = __floats2half2_rn(o0, o1);
                    long roff = ((seg == 1 || seg == 3) ? kroffA : kroffB) + gr;
                    if (seg <= 2)
                        *(__half2*)&g_krh[roff * 128 + cc] = hv;
                    else
                        *(__half2*)&g_vrh[roff * 128 + cc] = hv;
                }
            }
        }
    }
}

// combined out GEMM: one launch covers all 3 types
__global__ __launch_bounds__(256)
void mma_out_kernel(int l, float* __restrict__ Cbase,
                    const float* __restrict__ Xbase,
                    const float* __restrict__ bout,
                    const float* __restrict__ skip, int xsplit) {
    extern __shared__ __align__(16) __nv_bfloat16 smem[];
    int bid = blockIdx.x;
    int t, mt;
    if (bid < MT0)            { t = 0; mt = bid; }
    else if (bid < MT0 + MT1) { t = 1; mt = bid - MT0; }
    else                      { t = 2; mt = bid - MT0 - MT1; }

    int M = (t == 0) ? 50000 : (t == 1 ? 20000 : 10000);
    long offs = (t == 0) ? 0 : (t == 1 ? 50000 : 70000);
    int bm = mt * 128;
    int lt = l * NTYPE + t;

    float acc[4][4][4];
    gemm_core(offs, (long)W2TOT + (long)lt * FF * FF, bm, 0, M, smem, acc);

    int lane = threadIdx.x & 31, wid = threadIdx.x >> 5;
    int wm = (wid & 1) * 64, wn = (wid >> 1) * 32;
    const float* bias = bout + (long)lt * FF;
    float sv = skip[lt];
    float s = 1.f / (1.f + expf(-sv));
    float oms = 1.f - s;
    float* C = Cbase + offs * FF;
    const float* X = Xbase + offs * FF;
#pragma unroll
    for (int mi = 0; mi < 4; mi++) {
#pragma unroll
        for (int nj = 0; nj < 4; nj++) {
            int rbase = bm + wm + mi * 16 + (lane >> 2);
            int col = wn + nj * 8 + (lane & 3) * 2;
            float2 b2 = *(const float2*)&bias[col];
#pragma unroll
            for (int h = 0; h < 2; h++) {
                int gr = rbase + h * 8;
                if (gr >= M) continue;
                float o0 = acc[mi][nj][h * 2 + 0] + b2.x;
                float o1 = acc[mi][nj][h * 2 + 1] + b2.y;
                float2 xv = *(const float2*)&X[(long)gr * 128 + col];
                float n0 = s * o0 + oms * xv.x;
                float n1 = s * o1 + oms * xv.y;
                float r0 = fmaxf(n0, 0.f) + xv.x;
                float r1 = fmaxf(n1, 0.f) + xv.y;
                *(float2*)&C[(long)gr * 128 + col] = make_float2(r0, r1);
                if (xsplit) {
                    long pidx = (offs + gr) * 128 + col;
                    __nv_bfloat16 h0 = __float2bfloat16_rn(r0);
                    __nv_bfloat16 h1 = __float2bfloat16_rn(r1);
                    __nv_bfloat16 l0 = __float2bfloat16_rn(r0 - __bfloat162float(h0));
                    __nv_bfloat16 l1 = __float2bfloat16_rn(r1 - __bfloat162float(h1));
                    __nv_bfloat162 hv; hv.x = h0; hv.y = h1;
                    __nv_bfloat162 lv; lv.x = l0; lv.y = l1;
                    *(__nv_bfloat162*)&g_ah[pidx] = hv;
                    *(__nv_bfloat162*)&g_al[pidx] = lv;
                }
            }
        }
    }
}

// ---------------- fused edge phase (head-per-lane, no in-loop shuffles) ----
__device__ __forceinline__ void unpack8(uint4 u, float* f) {
    float2 a = __half22float2(*(__half2*)&u.x);
    float2 b = __half22float2(*(__half2*)&u.y);
    float2 c = __half22float2(*(__half2*)&u.z);
    float2 d = __half22float2(*(__half2*)&u.w);
    f[0] = a.x; f[1] = a.y; f[2] = b.x; f[3] = b.y;
    f[4] = c.x; f[5] = c.y; f[6] = d.x; f[7] = d.y;
}

__global__ __launch_bounds__(256)
void edge_fused_kernel(const float* __restrict__ prel, int l) {
    int warp = (blockIdx.x * blockDim.x + threadIdx.x) >> 5;
    int lane = threadIdx.x & 31;
    if (warp >= NTOT) return;
    int g = lane >> 3;      // edge slot 0..3
    int h = lane & 7;       // head
    int o0 = g_off[warp], o1 = g_off[warp + 1];

    // q for head h: 16 floats
    float q[16];
    const float4* qp = (const float4*)(g_q + (long)warp * FF + h * 16);
#pragma unroll
    for (int i = 0; i < 4; i++) *(float4*)&q[i * 4] = qp[i];

    float prh[NREL];
#pragma unroll
    for (int r = 0; r < NREL; r++)
        prh[r] = prel[(l * NREL + r) * HH + h] * 0.25f;

    float acc[16];
#pragma unroll
    for (int i = 0; i < 16; i++) acc[i] = 0.f;
    float denom = 0.f;

    for (int base = o0; base < o1; base += 4) {
        int j = base + g;
        bool act = (j < o1);
        int cv = act ? g_csr[j] : g_csr[base];
        long row = (long)(cv & 0xFFFFF) * FF + h * 16;
        int rel = cv >> 20;
        uint4 k0 = *(const uint4*)(g_krh + row);
        uint4 k1 = *(const uint4*)(g_krh + row + 8);
        uint4 v0 = *(const uint4*)(g_vrh + row);
        uint4 v1 = *(const uint4*)(g_vrh + row + 8);
        float kf[16];
        unpack8(k0, kf);
        unpack8(k1, kf + 8);
        float p = 0.f;
#pragma unroll
        for (int i = 0; i < 16; i++) p += q[i] * kf[i];
        float ex = act ? __expf(p * prh[rel]) : 0.f;
        float vf[16];
        unpack8(v0, vf);
        unpack8(v1, vf + 8);
#pragma unroll
        for (int i = 0; i < 16; i++) acc[i] += ex * vf[i];
        denom += ex;
    }

    // reduce across the 4 edge slots (lanes differing in bits 3-4)
#pragma unroll
    for (int i = 0; i < 16; i++) {
        acc[i] += __shfl_xor_sync(0xFFFFFFFFu, acc[i], 8);
        acc[i] += __shfl_xor_sync(0xFFFFFFFFu, acc[i], 16);
    }
    denom += __shfl_xor_sync(0xFFFFFFFFu, denom, 8);
    denom += __shfl_xor_sync(0xFFFFFFFFu, denom, 16);

    if (g == 0) {
        float inv = (o1 > o0) ? 1.f / denom : 0.f;
        __nv_bfloat16 hb[16], lb[16];
#pragma unroll
        for (int i = 0; i < 16; i++) {
            float o = gelu_f(acc[i] * inv);
            hb[i] = __float2bfloat16_rn(o);
            lb[i] = __float2bfloat16_rn(o - __bfloat162float(hb[i]));
        }
        long idx = (long)warp * FF + h * 16;
        *(uint4*)&g_ah[idx]     = *(const uint4*)&hb[0];
        *(uint4*)&g_ah[idx + 8] = *(const uint4*)&hb[8];
        *(uint4*)&g_al[idx]     = *(const uint4*)&lb[0];
        *(uint4*)&g_al[idx + 8] = *(const uint4*)&lb[8];
    }
}

// ---------------- launch ----------------
extern "C" void kernel_launch(void* const* d_in, const int* in_sizes, int n_in,
                              void* d_out, int out_size) {
    const float* xg   = (const float*)d_in[0];
    const float* xd   = (const float*)d_in[1];
    const float* xr   = (const float*)d_in[2];
    const float* Wkqv = (const float*)d_in[3];
    const float* bkqv = (const float*)d_in[4];
    const float* Ak   = (const float*)d_in[5];
    const float* Av   = (const float*)d_in[6];
    const float* prel = (const float*)d_in[7];
    const float* Wout = (const float*)d_in[8];
    const float* bout = (const float*)d_in[9];
    const float* skip = (const float*)d_in[10];
    const int* e0 = (const int*)d_in[11];
    const int* e1 = (const int*)d_in[12];
    const int* e2 = (const int*)d_in[13];
    const int* e3 = (const int*)d_in[14];
    float* outp = (float*)d_out;

    const int SPLIT_BLOCKS = (NTOT * FF / 8 + 255) / 256;

    float* d_x0; cudaGetSymbolAddress((void**)&d_x0, g_x0);
    float* d_x1; cudaGetSymbolAddress((void**)&d_x1, g_x1);

    cudaFuncSetAttribute(mma_qkv_kernel, cudaFuncAttributeMaxDynamicSharedMemorySize, GEMM_SMEM);
    cudaFuncSetAttribute(mma_out_kernel, cudaFuncAttributeMaxDynamicSharedMemorySize, GEMM_SMEM);

    copyin_split_kernel<<<SPLIT_BLOCKS, 256>>>(xg, xd, xr);
    fold_kernel<<<(W2TOT + 255) / 256, 256>>>(Wkqv, Ak, Av);
    foldb_kernel<<<(NLAYER * NTYPE * 5 * FF + 255) / 256, 256>>>(bkqv, Ak, Av);
    splitw_kernel<<<(OUTW_ELEMS + 255) / 256, 256>>>(Wout);

    zero_deg_kernel<<<(NTOT + 255) / 256, 256>>>();
    hist_all_kernel<<<(ETOT + 255) / 256, 256>>>(e0, e1, e2, e3);
    scan_kernel<<<1, 1024>>>();
    scatter_all_kernel<<<(ETOT + 255) / 256, 256>>>(e0, e1, e2, e3);

    for (int l = 0; l < NLAYER; l++) {
        mma_qkv_kernel<<<QKV_BLOCKS, 256, GEMM_SMEM>>>(l);
        edge_fused_kernel<<<NTOT / 8, 256>>>(prel, l);
        float* cdst = (l == 0) ? d_x1 : outp;
        const float* xcur = (l == 0) ? d_x0 : d_x1;
        mma_out_kernel<<<OUT_BLOCKS, 256, GEMM_SMEM>>>(
            l, cdst, xcur, bout, skip, (l == 0) ? 1 : 0);
    }
    (void)in_sizes; (void)n_in; (void)out_size;
}